// round 6
// baseline (speedup 1.0000x reference)
#include <cuda_runtime.h>
#include <math.h>

#define BATCH 1024
#define WSZ   8192
#define DIN   65
#define NA    66
#define IRL   16382
#define MI_N  513
#define INV_MAXSTEPS (1.0f/2799.0f)
#define PI_OVER_8191 (3.14159265358979323846f/8191.0f)

__device__ float        g_mean[BATCH];
__device__ float        g_amps[BATCH];
__device__ unsigned int g_max_u;
__device__ float        g_D[MI_N * NA];   // windowed DCT columns [mi][i], h folded
__device__ float        g_P[NA * WSZ];    // conv result [i][t]

__device__ __forceinline__ unsigned f2tf32(float f) {
    unsigned u;
    asm("cvt.rna.tf32.f32 %0, %1;" : "=r"(u) : "f"(f));
    return u;
}
__device__ __forceinline__ float cos_ph(int p) {   // p in [0, IRL)
    int p2 = (p >= 8191) ? (p - IRL) : p;
    return __cosf((float)p2 * PI_OVER_8191);
}

// ---------------------------------------------------------------------------
__global__ void k_init() {
    int idx = blockIdx.x * blockDim.x + threadIdx.x;
    if (idx < MI_N * NA) g_D[idx] = 0.0f;
    if (idx == 0)        g_max_u = 0u;
}

// ---------------------------------------------------------------------------
// Center column mi=512 (m=8191): cos = (-1)^k, h=1. Split-k x8 + atomicAdd.
__global__ void k_center(const float* __restrict__ Wc, const float* __restrict__ bc) {
    __shared__ float red[8];
    int i = blockIdx.x;
    int kc = blockIdx.y * 1024;
    const float* row = (i < DIN) ? &Wc[i * WSZ] : bc;
    float s = 0.0f;
    for (int k = kc + threadIdx.x; k < kc + 1024; k += 256) {
        float gk = (k == 0 || k == WSZ - 1) ? 1.0f : 2.0f;
        float sgn = (k & 1) ? -1.0f : 1.0f;
        s += row[k] * gk * sgn;
    }
    #pragma unroll
    for (int o = 16; o; o >>= 1) s += __shfl_xor_sync(0xffffffffu, s, o);
    if ((threadIdx.x & 31) == 0) red[threadIdx.x >> 5] = s;
    __syncthreads();
    if (threadIdx.x == 0) {
        float t = 0.0f;
        #pragma unroll
        for (int w = 0; w < 8; w++) t += red[w];
        atomicAdd(&g_D[512 * NA + i], t * (1.0f / 16382.0f));
    }
}

// ---------------------------------------------------------------------------
__global__ void k_stats(const float* __restrict__ vel, const float* __restrict__ Kin,
                        const float* __restrict__ Wa, const float* __restrict__ ba,
                        const float* __restrict__ Wm, const float* __restrict__ bm,
                        float* __restrict__ out, int out_size) {
    int gw = (blockIdx.x * blockDim.x + threadIdx.x) >> 5;
    int lane = threadIdx.x & 31;
    if (gw >= BATCH) return;
    float sa = 0.0f, sm = 0.0f;
    #pragma unroll
    for (int i = lane; i < 64; i += 32) {
        float x = vel[gw * 64 + i];
        sa += x * Wa[i];
        sm += x * Wm[i];
    }
    if (lane == 0) {
        float xk = Kin[gw] * INV_MAXSTEPS;
        sa += xk * Wa[64];
        sm += xk * Wm[64];
    }
    #pragma unroll
    for (int o = 16; o; o >>= 1) {
        sa += __shfl_down_sync(0xffffffffu, sa, o);
        sm += __shfl_down_sync(0xffffffffu, sm, o);
    }
    if (lane == 0) {
        float m = tanhf(sm + bm[0]);
        float a = 1.0f / (1.0f + expf(-(sa + ba[0])));
        g_mean[gw] = m;
        g_amps[gw] = a;
        if (out_size >= BATCH * WSZ + BATCH)
            out[BATCH * WSZ + gw] = m;
    }
}

// ---------------------------------------------------------------------------
__global__ void k_gmax(const float* __restrict__ eps) {
    const int N4 = (BATCH * WSZ) / 4;
    const float NEG = __int_as_float(0xff800000);
    int stride = gridDim.x * blockDim.x;
    int i0 = blockIdx.x * blockDim.x + threadIdx.x;
    const float4* e4 = reinterpret_cast<const float4*>(eps);
    float a0 = NEG, a1 = NEG, a2 = NEG, a3 = NEG;
    for (int j = i0; j < N4; j += 4 * stride) {
        int j1 = j + stride, j2 = j + 2 * stride, j3 = j + 3 * stride;
        float4 v0 = e4[j];
        float4 v1 = (j1 < N4) ? e4[j1] : make_float4(NEG,NEG,NEG,NEG);
        float4 v2 = (j2 < N4) ? e4[j2] : make_float4(NEG,NEG,NEG,NEG);
        float4 v3 = (j3 < N4) ? e4[j3] : make_float4(NEG,NEG,NEG,NEG);
        float m0 = g_mean[j >> 11];
        float m1 = (j1 < N4) ? g_mean[j1 >> 11] : 0.0f;
        float m2 = (j2 < N4) ? g_mean[j2 >> 11] : 0.0f;
        float m3 = (j3 < N4) ? g_mean[j3 >> 11] : 0.0f;
        a0 = fmaxf(a0, m0 + fmaxf(fmaxf(v0.x, v0.y), fmaxf(v0.z, v0.w)));
        a1 = fmaxf(a1, m1 + fmaxf(fmaxf(v1.x, v1.y), fmaxf(v1.z, v1.w)));
        a2 = fmaxf(a2, m2 + fmaxf(fmaxf(v2.x, v2.y), fmaxf(v2.z, v2.w)));
        a3 = fmaxf(a3, m3 + fmaxf(fmaxf(v3.x, v3.y), fmaxf(v3.z, v3.w)));
    }
    float lm = fmaxf(fmaxf(a0, a1), fmaxf(a2, a3));
    #pragma unroll
    for (int o = 16; o; o >>= 1)
        lm = fmaxf(lm, __shfl_xor_sync(0xffffffffu, lm, o));
    if ((threadIdx.x & 31) == 0) {
        unsigned b = __float_as_uint(lm);
        unsigned enc = (b & 0x80000000u) ? ~b : (b | 0x80000000u);
        atomicMax(&g_max_u, enc);
    }
}

// ---------------------------------------------------------------------------
// Double-folded DCT with Chebyshev cosine recurrence (MUFU only for seeds).
#define MM_KSPLIT 64
#define MM_SUB 32
__global__ void __launch_bounds__(288) k_mmat(const float* __restrict__ Wc,
                                              const float* __restrict__ bc) {
    __shared__ float sWe[MM_SUB * 76];
    __shared__ float sWo[MM_SUB * 76];
    __shared__ float sC[MM_SUB * 128];
    int tid = threadIdx.x;
    int tx = tid & 31;
    int iy = tid >> 5;
    int mi0 = blockIdx.x * 128;
    int k0  = blockIdx.y * 64;

    // Chebyshev state: thread (tid<256) owns mi = mi0 + (tid&127),
    // fills kk = half + 2s with step angle 2*mmf.
    int mfill = tid & 127;
    int half  = (tid >> 7) & 1;
    float x0 = 0.f, x1 = 0.f, tc = 0.f;
    if (tid < 256) {
        int mmf = 7679 + mi0 + mfill;
        int stepk = 2 * mmf; if (stepk >= IRL) stepk -= IRL;
        int ph0 = (int)(((long long)(k0 + half) * (long long)mmf) % IRL);
        int ph1 = ph0 + stepk; if (ph1 >= IRL) ph1 -= IRL;
        x0 = cos_ph(ph0);
        x1 = cos_ph(ph1);
        tc = 2.0f * cos_ph(stepk);
    }

    float acc[8][4];
    #pragma unroll
    for (int q = 0; q < 8; q++)
        #pragma unroll
        for (int r = 0; r < 4; r++) acc[q][r] = 0.0f;

    for (int c = 0; c < 64 / MM_SUB; c++) {
        int kc = k0 + c * MM_SUB;
        __syncthreads();
        for (int idx = tid; idx < 72 * MM_SUB; idx += 288) {
            int i = idx >> 5, kk = idx & 31;
            int k = kc + kk, kb = 8191 - k;
            float va = (i < DIN) ? Wc[i * WSZ + k]  : (i == DIN ? bc[k]  : 0.0f);
            float vb = (i < DIN) ? Wc[i * WSZ + kb] : (i == DIN ? bc[kb] : 0.0f);
            float ga = (k == 0) ? 1.0f : 2.0f;
            float gb = (kb == WSZ - 1) ? 1.0f : 2.0f;
            sWe[kk * 76 + i] = va * ga + vb * gb;
            sWo[kk * 76 + i] = va * ga - vb * gb;
        }
        if (tid < 256) {
            #pragma unroll
            for (int s = 0; s < 16; s++) {
                sC[(half + 2 * s) * 128 + mfill] = x0;
                float nx = fmaf(tc, x1, -x0);
                x0 = x1; x1 = nx;
            }
        }
        __syncthreads();
        #pragma unroll 8
        for (int kk = 0; kk < MM_SUB; kk++) {
            float4 cv = *reinterpret_cast<const float4*>(&sC[kk * 128 + tx * 4]);
            float4 ea = *reinterpret_cast<const float4*>(&sWe[kk * 76 + iy * 8]);
            float4 eb = *reinterpret_cast<const float4*>(&sWe[kk * 76 + iy * 8 + 4]);
            float4 oa = *reinterpret_cast<const float4*>(&sWo[kk * 76 + iy * 8]);
            float4 ob = *reinterpret_cast<const float4*>(&sWo[kk * 76 + iy * 8 + 4]);
            float ev[8] = {ea.x, ea.y, ea.z, ea.w, eb.x, eb.y, eb.z, eb.w};
            float ov[8] = {oa.x, oa.y, oa.z, oa.w, ob.x, ob.y, ob.z, ob.w};
            #pragma unroll
            for (int q = 0; q < 8; q++) {
                acc[q][0] = fmaf(ov[q], cv.x, acc[q][0]);
                acc[q][1] = fmaf(ev[q], cv.y, acc[q][1]);
                acc[q][2] = fmaf(ov[q], cv.z, acc[q][2]);
                acc[q][3] = fmaf(ev[q], cv.w, acc[q][3]);
            }
        }
    }

    #pragma unroll
    for (int r = 0; r < 4; r++) {
        int mi = mi0 + tx * 4 + r;
        int jh = (mi >= 2) ? (mi - 2) : (1022 - mi);
        float h = 0.5f - 0.5f * cospif((float)(jh + 2) * (1.0f / 512.0f));
        float sc = h * (1.0f / 16382.0f);
        #pragma unroll
        for (int q = 0; q < 8; q++) {
            int i = iy * 8 + q;
            if (i < NA)
                atomicAdd(&g_D[mi * NA + i], acc[q][r] * sc);
        }
    }
}

// ---------------------------------------------------------------------------
// Tensor-core folded FIR: P[i][t] = sum_dd Cf[dd][i] * F[dd][t]
//   dd 0..509: d=dd+1, Cf = D[511-dd], F = n(t+d)+n(t-d)
//   dd 510: Cf = D[512], F = n(t);  dd 511: Cf = D[1], F = n(t-511)
//   dd 512: Cf = D[0], F = n(t-512); dd 513..543: zero
// Block: 128 thr (4 warps x 16 t), t-tile 64, grid 128. No atomics.
#define CV_TT 64
__global__ void __launch_bounds__(128) k_conv_tc(const float* __restrict__ eps) {
    __shared__ float    sN[1088];
    __shared__ unsigned sF[32 * 72];    // [dd][t]
    __shared__ unsigned sCf[32 * 72];   // [dd][i]
    int tid = threadIdx.x;
    int lane = tid & 31, w = tid >> 5;
    int t0 = blockIdx.x * CV_TT;

    float mean0 = g_mean[0];
    unsigned encm = g_max_u;
    float gmax = (encm & 0x80000000u) ? __uint_as_float(encm & 0x7fffffffu)
                                      : __uint_as_float(~encm);
    float inv = 1.0f / gmax;
    for (int s = tid; s < 1088; s += 128) {
        int u = t0 - 512 + s;
        sN[s] = (u >= 0 && u < WSZ) ? (mean0 + eps[u]) * inv : 0.0f;
    }

    int r = lane >> 2, cq = lane & 3;
    int tw = w * 16;
    float acc[9][4];
    #pragma unroll
    for (int nf = 0; nf < 9; nf++)
        #pragma unroll
        for (int q = 0; q < 4; q++) acc[nf][q] = 0.0f;

    for (int c = 0; c < 17; c++) {
        int dd0 = 32 * c;
        __syncthreads();
        for (int idx = tid; idx < 32 * CV_TT; idx += 128) {
            int ddl = idx >> 6, tt = idx & 63;
            int dd = dd0 + ddl;
            int x = 512 + tt;
            float f;
            if (dd < 510)       { int d = dd + 1; f = sN[x + d] + sN[x - d]; }
            else if (dd == 510) f = sN[x];
            else if (dd == 511) f = sN[x - 511];
            else if (dd == 512) f = sN[x - 512];
            else                f = 0.0f;
            sF[ddl * 72 + tt] = f2tf32(f);
        }
        for (int idx = tid; idx < 32 * 72; idx += 128) {
            int ddl = idx / 72, i = idx % 72;
            int dd = dd0 + ddl;
            int mi;
            if (dd < 510)       mi = 511 - dd;
            else if (dd == 510) mi = 512;
            else if (dd == 511) mi = 1;
            else if (dd == 512) mi = 0;
            else                mi = -1;
            float v = (mi >= 0 && i < NA) ? g_D[mi * NA + i] : 0.0f;
            sCf[ddl * 72 + i] = f2tf32(v);
        }
        __syncthreads();
        #pragma unroll
        for (int ks = 0; ks < 4; ks++) {
            int k0 = ks * 8;
            unsigned a0 = sF[(k0 + cq) * 72 + tw + r];
            unsigned a1 = sF[(k0 + cq) * 72 + tw + r + 8];
            unsigned a2 = sF[(k0 + cq + 4) * 72 + tw + r];
            unsigned a3 = sF[(k0 + cq + 4) * 72 + tw + r + 8];
            #pragma unroll
            for (int nf = 0; nf < 9; nf++) {
                unsigned b0 = sCf[(k0 + cq) * 72 + nf * 8 + r];
                unsigned b1 = sCf[(k0 + cq + 4) * 72 + nf * 8 + r];
                asm volatile(
                    "mma.sync.aligned.m16n8k8.row.col.f32.tf32.tf32.f32 "
                    "{%0,%1,%2,%3}, {%4,%5,%6,%7}, {%8,%9}, {%0,%1,%2,%3};"
                    : "+f"(acc[nf][0]), "+f"(acc[nf][1]),
                      "+f"(acc[nf][2]), "+f"(acc[nf][3])
                    : "r"(a0), "r"(a1), "r"(a2), "r"(a3),
                      "r"(b0), "r"(b1));
            }
        }
    }

    int t = t0 + tw + r;
    #pragma unroll
    for (int nf = 0; nf < 9; nf++) {
        int i0 = nf * 8 + 2 * cq;
        if (i0 < NA) {
            g_P[i0 * WSZ + t]     = acc[nf][0];
            g_P[i0 * WSZ + t + 8] = acc[nf][2];
        }
        if (i0 + 1 < NA) {
            g_P[(i0 + 1) * WSZ + t]     = acc[nf][1];
            g_P[(i0 + 1) * WSZ + t + 8] = acc[nf][3];
        }
    }
}

// ---------------------------------------------------------------------------
// k_out via tf32 mma (unchanged from R5).
#define KO_BT 64
#define KO_TT 128
#define KO_K  72
#define PST 136
#define XST 76
#define KO_SMEM ((KO_K * PST + KO_BT * XST) * 4 + KO_BT * 4)

extern __shared__ unsigned ko_smem[];
__global__ void __launch_bounds__(256) k_out_tc(const float* __restrict__ vel,
                                                const float* __restrict__ Kin,
                                                float* __restrict__ out) {
    unsigned* sP = ko_smem;
    unsigned* sX = ko_smem + KO_K * PST;
    float*    sA = (float*)(sX + KO_BT * XST);
    int tid = threadIdx.x, lane = tid & 31, w = tid >> 5;
    int t0 = blockIdx.x * KO_TT, b0 = blockIdx.y * KO_BT;

    for (int idx = tid; idx < KO_K * KO_TT; idx += 256) {
        int i = idx >> 7, tt = idx & 127;
        float v = (i < NA) ? g_P[i * WSZ + t0 + tt] : 0.0f;
        sP[i * PST + tt] = f2tf32(v);
    }
    for (int idx = tid; idx < KO_BT * KO_K; idx += 256) {
        int bb = idx / KO_K, i = idx % KO_K;
        int b = b0 + bb;
        float x;
        if (i < 64)       x = vel[b * 64 + i];
        else if (i == 64) x = Kin[b] * INV_MAXSTEPS;
        else if (i == 65) x = 1.0f;
        else              x = 0.0f;
        sX[bb * XST + i] = f2tf32(x);
    }
    if (tid < KO_BT) sA[tid] = g_amps[b0 + tid];
    __syncthreads();

    int wb = w & 1, wt = w >> 1;
    int r = lane >> 2, cq = lane & 3;
    float c[2][4][4];
    #pragma unroll
    for (int mf = 0; mf < 2; mf++)
        #pragma unroll
        for (int nf = 0; nf < 4; nf++)
            #pragma unroll
            for (int q = 0; q < 4; q++) c[mf][nf][q] = 0.0f;

    #pragma unroll
    for (int s = 0; s < KO_K / 8; s++) {
        int k0 = s * 8;
        unsigned a[2][4];
        #pragma unroll
        for (int mf = 0; mf < 2; mf++) {
            int rb = wb * 32 + mf * 16 + r;
            a[mf][0] = sX[rb * XST + k0 + cq];
            a[mf][1] = sX[(rb + 8) * XST + k0 + cq];
            a[mf][2] = sX[rb * XST + k0 + cq + 4];
            a[mf][3] = sX[(rb + 8) * XST + k0 + cq + 4];
        }
        unsigned bf[4][2];
        #pragma unroll
        for (int nf = 0; nf < 4; nf++) {
            int ct = wt * 32 + nf * 8 + r;
            bf[nf][0] = sP[(k0 + cq) * PST + ct];
            bf[nf][1] = sP[(k0 + cq + 4) * PST + ct];
        }
        #pragma unroll
        for (int mf = 0; mf < 2; mf++)
            #pragma unroll
            for (int nf = 0; nf < 4; nf++) {
                asm volatile(
                    "mma.sync.aligned.m16n8k8.row.col.f32.tf32.tf32.f32 "
                    "{%0,%1,%2,%3}, {%4,%5,%6,%7}, {%8,%9}, {%0,%1,%2,%3};"
                    : "+f"(c[mf][nf][0]), "+f"(c[mf][nf][1]),
                      "+f"(c[mf][nf][2]), "+f"(c[mf][nf][3])
                    : "r"(a[mf][0]), "r"(a[mf][1]), "r"(a[mf][2]), "r"(a[mf][3]),
                      "r"(bf[nf][0]), "r"(bf[nf][1]));
            }
    }

    #pragma unroll
    for (int mf = 0; mf < 2; mf++) {
        int rbl = wb * 32 + mf * 16 + r;
        float a1 = sA[rbl], a2 = sA[rbl + 8];
        int rb = b0 + rbl;
        #pragma unroll
        for (int nf = 0; nf < 4; nf++) {
            int ct = t0 + wt * 32 + nf * 8 + 2 * cq;
            float2 o1 = make_float2(a1 * c[mf][nf][0], a1 * c[mf][nf][1]);
            float2 o2 = make_float2(a2 * c[mf][nf][2], a2 * c[mf][nf][3]);
            *reinterpret_cast<float2*>(&out[rb * WSZ + ct])       = o1;
            *reinterpret_cast<float2*>(&out[(rb + 8) * WSZ + ct]) = o2;
        }
    }
}

// ---------------------------------------------------------------------------
static cudaStream_t s_aux1, s_aux2;
static cudaEvent_t  ev_root, ev_j1, ev_j2;
namespace {
struct StreamBoot {
    StreamBoot() {
        cudaStreamCreateWithFlags(&s_aux1, cudaStreamNonBlocking);
        cudaStreamCreateWithFlags(&s_aux2, cudaStreamNonBlocking);
        cudaEventCreateWithFlags(&ev_root, cudaEventDisableTiming);
        cudaEventCreateWithFlags(&ev_j1,   cudaEventDisableTiming);
        cudaEventCreateWithFlags(&ev_j2,   cudaEventDisableTiming);
    }
};
static StreamBoot g_stream_boot;
}

extern "C" void kernel_launch(void* const* d_in, const int* in_sizes, int n_in,
                              void* d_out, int out_size) {
    const float* vel = (const float*)d_in[0];
    const float* Kin = (const float*)d_in[1];
    const float* eps = (const float*)d_in[2];
    const float* Wc  = (const float*)d_in[3];
    const float* bc  = (const float*)d_in[4];
    const float* Wa  = (const float*)d_in[5];
    const float* ba  = (const float*)d_in[6];
    const float* Wm  = (const float*)d_in[7];
    const float* bm  = (const float*)d_in[8];
    float* out = (float*)d_out;

    cudaFuncSetAttribute(k_out_tc, cudaFuncAttributeMaxDynamicSharedMemorySize, KO_SMEM);

    k_init  <<< (MI_N * NA + 255) / 256, 256 >>> ();
    cudaEventRecord(ev_root, 0);
    cudaStreamWaitEvent(s_aux1, ev_root, 0);
    cudaStreamWaitEvent(s_aux2, ev_root, 0);

    k_stats <<< 32, 1024, 0, s_aux1 >>> (vel, Kin, Wa, ba, Wm, bm, out, out_size);
    k_gmax  <<< 1024, 256, 0, s_aux1 >>> (eps);
    cudaEventRecord(ev_j1, s_aux1);

    k_center<<< dim3(NA, 8), 256, 0, s_aux2 >>> (Wc, bc);
    cudaEventRecord(ev_j2, s_aux2);

    k_mmat  <<< dim3(4, MM_KSPLIT), 288 >>> (Wc, bc);
    cudaStreamWaitEvent(0, ev_j1, 0);
    cudaStreamWaitEvent(0, ev_j2, 0);
    k_conv_tc<<< WSZ / CV_TT, 128 >>> (eps);
    k_out_tc<<< dim3(WSZ / KO_TT, BATCH / KO_BT), 256, KO_SMEM >>> (vel, Kin, out);
}

// round 7
// speedup vs baseline: 1.7691x; 1.7691x over previous
#include <cuda_runtime.h>
#include <math.h>

#define BATCH 1024
#define WSZ   8192
#define DIN   65
#define NA    66
#define IRL   16382
#define MI_N  513
#define INV_MAXSTEPS (1.0f/2799.0f)
#define PI_OVER_8191 (3.14159265358979323846f/8191.0f)

__device__ float        g_mean[BATCH];
__device__ float        g_amps[BATCH];
__device__ unsigned int g_max_u;
__device__ float        g_D[MI_N * NA];   // windowed DCT columns [mi][i], h folded
__device__ float        g_P[NA * WSZ];    // conv result [i][t]

__device__ __forceinline__ unsigned f2tf32(float f) {
    unsigned u;
    asm("cvt.rna.tf32.f32 %0, %1;" : "=r"(u) : "f"(f));
    return u;
}
__device__ __forceinline__ float cos_ph(int p) {   // p in [0, IRL)
    int p2 = (p >= 8191) ? (p - IRL) : p;
    return __cosf((float)p2 * PI_OVER_8191);
}

// ---------------------------------------------------------------------------
__global__ void k_init() {
    int idx = blockIdx.x * blockDim.x + threadIdx.x;
    if (idx < (NA * WSZ) / 4)
        reinterpret_cast<float4*>(g_P)[idx] = make_float4(0.f, 0.f, 0.f, 0.f);
    if (idx < MI_N * NA) g_D[idx] = 0.0f;
    if (idx == 0)        g_max_u = 0u;
}

// ---------------------------------------------------------------------------
// Center column mi=512 (m=8191): cos = (-1)^k, h=1. Split-k x8 + atomicAdd.
__global__ void k_center(const float* __restrict__ Wc, const float* __restrict__ bc) {
    __shared__ float red[8];
    int i = blockIdx.x;
    int kc = blockIdx.y * 1024;
    const float* row = (i < DIN) ? &Wc[i * WSZ] : bc;
    float s = 0.0f;
    for (int k = kc + threadIdx.x; k < kc + 1024; k += 256) {
        float gk = (k == 0 || k == WSZ - 1) ? 1.0f : 2.0f;
        float sgn = (k & 1) ? -1.0f : 1.0f;
        s += row[k] * gk * sgn;
    }
    #pragma unroll
    for (int o = 16; o; o >>= 1) s += __shfl_xor_sync(0xffffffffu, s, o);
    if ((threadIdx.x & 31) == 0) red[threadIdx.x >> 5] = s;
    __syncthreads();
    if (threadIdx.x == 0) {
        float t = 0.0f;
        #pragma unroll
        for (int w = 0; w < 8; w++) t += red[w];
        atomicAdd(&g_D[512 * NA + i], t * (1.0f / 16382.0f));
    }
}

// ---------------------------------------------------------------------------
__global__ void k_stats(const float* __restrict__ vel, const float* __restrict__ Kin,
                        const float* __restrict__ Wa, const float* __restrict__ ba,
                        const float* __restrict__ Wm, const float* __restrict__ bm,
                        float* __restrict__ out, int out_size) {
    int gw = (blockIdx.x * blockDim.x + threadIdx.x) >> 5;
    int lane = threadIdx.x & 31;
    if (gw >= BATCH) return;
    float sa = 0.0f, sm = 0.0f;
    #pragma unroll
    for (int i = lane; i < 64; i += 32) {
        float x = vel[gw * 64 + i];
        sa += x * Wa[i];
        sm += x * Wm[i];
    }
    if (lane == 0) {
        float xk = Kin[gw] * INV_MAXSTEPS;
        sa += xk * Wa[64];
        sm += xk * Wm[64];
    }
    #pragma unroll
    for (int o = 16; o; o >>= 1) {
        sa += __shfl_down_sync(0xffffffffu, sa, o);
        sm += __shfl_down_sync(0xffffffffu, sm, o);
    }
    if (lane == 0) {
        float m = tanhf(sm + bm[0]);
        float a = 1.0f / (1.0f + expf(-(sa + ba[0])));
        g_mean[gw] = m;
        g_amps[gw] = a;
        if (out_size >= BATCH * WSZ + BATCH)
            out[BATCH * WSZ + gw] = m;
    }
}

// ---------------------------------------------------------------------------
__global__ void k_gmax(const float* __restrict__ eps) {
    const int N4 = (BATCH * WSZ) / 4;
    const float NEG = __int_as_float(0xff800000);
    int stride = gridDim.x * blockDim.x;
    int i0 = blockIdx.x * blockDim.x + threadIdx.x;
    const float4* e4 = reinterpret_cast<const float4*>(eps);
    float a0 = NEG, a1 = NEG, a2 = NEG, a3 = NEG;
    for (int j = i0; j < N4; j += 4 * stride) {
        int j1 = j + stride, j2 = j + 2 * stride, j3 = j + 3 * stride;
        float4 v0 = e4[j];
        float4 v1 = (j1 < N4) ? e4[j1] : make_float4(NEG,NEG,NEG,NEG);
        float4 v2 = (j2 < N4) ? e4[j2] : make_float4(NEG,NEG,NEG,NEG);
        float4 v3 = (j3 < N4) ? e4[j3] : make_float4(NEG,NEG,NEG,NEG);
        float m0 = g_mean[j >> 11];
        float m1 = (j1 < N4) ? g_mean[j1 >> 11] : 0.0f;
        float m2 = (j2 < N4) ? g_mean[j2 >> 11] : 0.0f;
        float m3 = (j3 < N4) ? g_mean[j3 >> 11] : 0.0f;
        a0 = fmaxf(a0, m0 + fmaxf(fmaxf(v0.x, v0.y), fmaxf(v0.z, v0.w)));
        a1 = fmaxf(a1, m1 + fmaxf(fmaxf(v1.x, v1.y), fmaxf(v1.z, v1.w)));
        a2 = fmaxf(a2, m2 + fmaxf(fmaxf(v2.x, v2.y), fmaxf(v2.z, v2.w)));
        a3 = fmaxf(a3, m3 + fmaxf(fmaxf(v3.x, v3.y), fmaxf(v3.z, v3.w)));
    }
    float lm = fmaxf(fmaxf(a0, a1), fmaxf(a2, a3));
    #pragma unroll
    for (int o = 16; o; o >>= 1)
        lm = fmaxf(lm, __shfl_xor_sync(0xffffffffu, lm, o));
    if ((threadIdx.x & 31) == 0) {
        unsigned b = __float_as_uint(lm);
        unsigned enc = (b & 0x80000000u) ? ~b : (b | 0x80000000u);
        atomicMax(&g_max_u, enc);
    }
}

// ---------------------------------------------------------------------------
// Double-folded DCT with Chebyshev cosine recurrence (MUFU only for seeds).
#define MM_KSPLIT 64
#define MM_SUB 32
__global__ void __launch_bounds__(288) k_mmat(const float* __restrict__ Wc,
                                              const float* __restrict__ bc) {
    __shared__ float sWe[MM_SUB * 76];
    __shared__ float sWo[MM_SUB * 76];
    __shared__ float sC[MM_SUB * 128];
    int tid = threadIdx.x;
    int tx = tid & 31;
    int iy = tid >> 5;
    int mi0 = blockIdx.x * 128;
    int k0  = blockIdx.y * 64;

    int mfill = tid & 127;
    int half  = (tid >> 7) & 1;
    float x0 = 0.f, x1 = 0.f, tc = 0.f;
    if (tid < 256) {
        int mmf = 7679 + mi0 + mfill;
        int stepk = 2 * mmf; if (stepk >= IRL) stepk -= IRL;
        int ph0 = (int)(((long long)(k0 + half) * (long long)mmf) % IRL);
        int ph1 = ph0 + stepk; if (ph1 >= IRL) ph1 -= IRL;
        x0 = cos_ph(ph0);
        x1 = cos_ph(ph1);
        tc = 2.0f * cos_ph(stepk);
    }

    float acc[8][4];
    #pragma unroll
    for (int q = 0; q < 8; q++)
        #pragma unroll
        for (int r = 0; r < 4; r++) acc[q][r] = 0.0f;

    for (int c = 0; c < 64 / MM_SUB; c++) {
        int kc = k0 + c * MM_SUB;
        __syncthreads();
        for (int idx = tid; idx < 72 * MM_SUB; idx += 288) {
            int i = idx >> 5, kk = idx & 31;
            int k = kc + kk, kb = 8191 - k;
            float va = (i < DIN) ? Wc[i * WSZ + k]  : (i == DIN ? bc[k]  : 0.0f);
            float vb = (i < DIN) ? Wc[i * WSZ + kb] : (i == DIN ? bc[kb] : 0.0f);
            float ga = (k == 0) ? 1.0f : 2.0f;
            float gb = (kb == WSZ - 1) ? 1.0f : 2.0f;
            sWe[kk * 76 + i] = va * ga + vb * gb;
            sWo[kk * 76 + i] = va * ga - vb * gb;
        }
        if (tid < 256) {
            #pragma unroll
            for (int s = 0; s < 16; s++) {
                sC[(half + 2 * s) * 128 + mfill] = x0;
                float nx = fmaf(tc, x1, -x0);
                x0 = x1; x1 = nx;
            }
        }
        __syncthreads();
        #pragma unroll 8
        for (int kk = 0; kk < MM_SUB; kk++) {
            float4 cv = *reinterpret_cast<const float4*>(&sC[kk * 128 + tx * 4]);
            float4 ea = *reinterpret_cast<const float4*>(&sWe[kk * 76 + iy * 8]);
            float4 eb = *reinterpret_cast<const float4*>(&sWe[kk * 76 + iy * 8 + 4]);
            float4 oa = *reinterpret_cast<const float4*>(&sWo[kk * 76 + iy * 8]);
            float4 ob = *reinterpret_cast<const float4*>(&sWo[kk * 76 + iy * 8 + 4]);
            float ev[8] = {ea.x, ea.y, ea.z, ea.w, eb.x, eb.y, eb.z, eb.w};
            float ov[8] = {oa.x, oa.y, oa.z, oa.w, ob.x, ob.y, ob.z, ob.w};
            #pragma unroll
            for (int q = 0; q < 8; q++) {
                acc[q][0] = fmaf(ov[q], cv.x, acc[q][0]);
                acc[q][1] = fmaf(ev[q], cv.y, acc[q][1]);
                acc[q][2] = fmaf(ov[q], cv.z, acc[q][2]);
                acc[q][3] = fmaf(ev[q], cv.w, acc[q][3]);
            }
        }
    }

    #pragma unroll
    for (int r = 0; r < 4; r++) {
        int mi = mi0 + tx * 4 + r;
        int jh = (mi >= 2) ? (mi - 2) : (1022 - mi);
        float h = 0.5f - 0.5f * cospif((float)(jh + 2) * (1.0f / 512.0f));
        float sc = h * (1.0f / 16382.0f);
        #pragma unroll
        for (int q = 0; q < 8; q++) {
            int i = iy * 8 + q;
            if (i < NA)
                atomicAdd(&g_D[mi * NA + i], acc[q][r] * sc);
        }
    }
}

// ---------------------------------------------------------------------------
// Folded symmetric FIR (fp32, proven fast in R4/R5):
// P[i][t] = D[512][i]*n0[t] + sum_{d=1..510} D[512-d][i]*(n0[t+d]+n0[t-d])
//           + D[1][i]*n0[t-511] + D[0][i]*n0[t-512]
#define K3_DSPLIT 4
__global__ void __launch_bounds__(288) k_conv(const float* __restrict__ eps) {
    __shared__ float sN[1152];
    __shared__ float sM[32 * 76];
    __shared__ float sF[32 * 132];
    int tid = threadIdx.x;
    int tx = tid & 31;
    int iy = tid >> 5;
    int t0 = blockIdx.x * 128;
    int y  = blockIdx.y;

    float mean0 = g_mean[0];
    unsigned enc = g_max_u;
    float gmax = (enc & 0x80000000u) ? __uint_as_float(enc & 0x7fffffffu)
                                     : __uint_as_float(~enc);
    float inv = 1.0f / gmax;
    for (int s = tid; s < 1152; s += 288) {
        int u = t0 - 512 + s;
        sN[s] = (u >= 0 && u < WSZ) ? (mean0 + eps[u]) * inv : 0.0f;
    }
    __syncthreads();

    float acc[8][4];
    #pragma unroll
    for (int q = 0; q < 8; q++)
        #pragma unroll
        for (int s = 0; s < 4; s++) acc[q][s] = 0.0f;

    if (y == 0) {
        #pragma unroll
        for (int q = 0; q < 8; q++) {
            int i = iy * 8 + q;
            if (i < NA) {
                float mC = g_D[512 * NA + i];
                float m1 = g_D[1 * NA + i];
                float m0 = g_D[0 * NA + i];
                #pragma unroll
                for (int s = 0; s < 4; s++) {
                    int x = 512 + tx * 4 + s;
                    acc[q][s] = mC * sN[x] + m1 * sN[x - 511] + m0 * sN[x - 512];
                }
            }
        }
    }

    for (int c = 0; c < 4; c++) {
        int d0 = 1 + 128 * y + 32 * c;
        __syncthreads();
        for (int idx = tid; idx < 32 * 72; idx += 288) {
            int dd = idx / 72, i = idx % 72;
            int mi = 512 - (d0 + dd);
            sM[dd * 76 + i] = (i < NA && mi >= 2) ? g_D[mi * NA + i] : 0.0f;
        }
        for (int idx = tid; idx < 32 * 128; idx += 288) {
            int dd = idx >> 7, tt = idx & 127;
            int d = d0 + dd;
            int x = 512 + tt;
            sF[dd * 132 + tt] = sN[x + d] + sN[x - d];
        }
        __syncthreads();
        #pragma unroll 8
        for (int dd = 0; dd < 32; dd++) {
            float4 fv = *reinterpret_cast<const float4*>(&sF[dd * 132 + tx * 4]);
            float4 ma = *reinterpret_cast<const float4*>(&sM[dd * 76 + iy * 8]);
            float4 mb = *reinterpret_cast<const float4*>(&sM[dd * 76 + iy * 8 + 4]);
            float mv[8] = {ma.x, ma.y, ma.z, ma.w, mb.x, mb.y, mb.z, mb.w};
            #pragma unroll
            for (int q = 0; q < 8; q++) {
                acc[q][0] = fmaf(mv[q], fv.x, acc[q][0]);
                acc[q][1] = fmaf(mv[q], fv.y, acc[q][1]);
                acc[q][2] = fmaf(mv[q], fv.z, acc[q][2]);
                acc[q][3] = fmaf(mv[q], fv.w, acc[q][3]);
            }
        }
    }

    #pragma unroll
    for (int q = 0; q < 8; q++) {
        int i = iy * 8 + q;
        if (i < NA) {
            #pragma unroll
            for (int s = 0; s < 4; s++)
                atomicAdd(&g_P[i * WSZ + t0 + tx * 4 + s], acc[q][s]);
        }
    }
}

// ---------------------------------------------------------------------------
// k_out via tf32 mma (unchanged from R5).
#define KO_BT 64
#define KO_TT 128
#define KO_K  72
#define PST 136
#define XST 76
#define KO_SMEM ((KO_K * PST + KO_BT * XST) * 4 + KO_BT * 4)

extern __shared__ unsigned ko_smem[];
__global__ void __launch_bounds__(256) k_out_tc(const float* __restrict__ vel,
                                                const float* __restrict__ Kin,
                                                float* __restrict__ out) {
    unsigned* sP = ko_smem;
    unsigned* sX = ko_smem + KO_K * PST;
    float*    sA = (float*)(sX + KO_BT * XST);
    int tid = threadIdx.x, lane = tid & 31, w = tid >> 5;
    int t0 = blockIdx.x * KO_TT, b0 = blockIdx.y * KO_BT;

    for (int idx = tid; idx < KO_K * KO_TT; idx += 256) {
        int i = idx >> 7, tt = idx & 127;
        float v = (i < NA) ? g_P[i * WSZ + t0 + tt] : 0.0f;
        sP[i * PST + tt] = f2tf32(v);
    }
    for (int idx = tid; idx < KO_BT * KO_K; idx += 256) {
        int bb = idx / KO_K, i = idx % KO_K;
        int b = b0 + bb;
        float x;
        if (i < 64)       x = vel[b * 64 + i];
        else if (i == 64) x = Kin[b] * INV_MAXSTEPS;
        else if (i == 65) x = 1.0f;
        else              x = 0.0f;
        sX[bb * XST + i] = f2tf32(x);
    }
    if (tid < KO_BT) sA[tid] = g_amps[b0 + tid];
    __syncthreads();

    int wb = w & 1, wt = w >> 1;
    int r = lane >> 2, cq = lane & 3;
    float c[2][4][4];
    #pragma unroll
    for (int mf = 0; mf < 2; mf++)
        #pragma unroll
        for (int nf = 0; nf < 4; nf++)
            #pragma unroll
            for (int q = 0; q < 4; q++) c[mf][nf][q] = 0.0f;

    #pragma unroll
    for (int s = 0; s < KO_K / 8; s++) {
        int k0 = s * 8;
        unsigned a[2][4];
        #pragma unroll
        for (int mf = 0; mf < 2; mf++) {
            int rb = wb * 32 + mf * 16 + r;
            a[mf][0] = sX[rb * XST + k0 + cq];
            a[mf][1] = sX[(rb + 8) * XST + k0 + cq];
            a[mf][2] = sX[rb * XST + k0 + cq + 4];
            a[mf][3] = sX[(rb + 8) * XST + k0 + cq + 4];
        }
        unsigned bf[4][2];
        #pragma unroll
        for (int nf = 0; nf < 4; nf++) {
            int ct = wt * 32 + nf * 8 + r;
            bf[nf][0] = sP[(k0 + cq) * PST + ct];
            bf[nf][1] = sP[(k0 + cq + 4) * PST + ct];
        }
        #pragma unroll
        for (int mf = 0; mf < 2; mf++)
            #pragma unroll
            for (int nf = 0; nf < 4; nf++) {
                asm volatile(
                    "mma.sync.aligned.m16n8k8.row.col.f32.tf32.tf32.f32 "
                    "{%0,%1,%2,%3}, {%4,%5,%6,%7}, {%8,%9}, {%0,%1,%2,%3};"
                    : "+f"(c[mf][nf][0]), "+f"(c[mf][nf][1]),
                      "+f"(c[mf][nf][2]), "+f"(c[mf][nf][3])
                    : "r"(a[mf][0]), "r"(a[mf][1]), "r"(a[mf][2]), "r"(a[mf][3]),
                      "r"(bf[nf][0]), "r"(bf[nf][1]));
            }
    }

    #pragma unroll
    for (int mf = 0; mf < 2; mf++) {
        int rbl = wb * 32 + mf * 16 + r;
        float a1 = sA[rbl], a2 = sA[rbl + 8];
        int rb = b0 + rbl;
        #pragma unroll
        for (int nf = 0; nf < 4; nf++) {
            int ct = t0 + wt * 32 + nf * 8 + 2 * cq;
            float2 o1 = make_float2(a1 * c[mf][nf][0], a1 * c[mf][nf][1]);
            float2 o2 = make_float2(a2 * c[mf][nf][2], a2 * c[mf][nf][3]);
            *reinterpret_cast<float2*>(&out[rb * WSZ + ct])       = o1;
            *reinterpret_cast<float2*>(&out[(rb + 8) * WSZ + ct]) = o2;
        }
    }
}

// ---------------------------------------------------------------------------
static cudaStream_t s_aux1, s_aux2;
static cudaEvent_t  ev_root, ev_j1, ev_j2;
namespace {
struct StreamBoot {
    StreamBoot() {
        cudaStreamCreateWithFlags(&s_aux1, cudaStreamNonBlocking);
        cudaStreamCreateWithFlags(&s_aux2, cudaStreamNonBlocking);
        cudaEventCreateWithFlags(&ev_root, cudaEventDisableTiming);
        cudaEventCreateWithFlags(&ev_j1,   cudaEventDisableTiming);
        cudaEventCreateWithFlags(&ev_j2,   cudaEventDisableTiming);
    }
};
static StreamBoot g_stream_boot;
}

extern "C" void kernel_launch(void* const* d_in, const int* in_sizes, int n_in,
                              void* d_out, int out_size) {
    const float* vel = (const float*)d_in[0];
    const float* Kin = (const float*)d_in[1];
    const float* eps = (const float*)d_in[2];
    const float* Wc  = (const float*)d_in[3];
    const float* bc  = (const float*)d_in[4];
    const float* Wa  = (const float*)d_in[5];
    const float* ba  = (const float*)d_in[6];
    const float* Wm  = (const float*)d_in[7];
    const float* bm  = (const float*)d_in[8];
    float* out = (float*)d_out;

    cudaFuncSetAttribute(k_out_tc, cudaFuncAttributeMaxDynamicSharedMemorySize, KO_SMEM);

    k_init  <<< (NA * WSZ / 4 + 255) / 256, 256 >>> ();
    cudaEventRecord(ev_root, 0);
    cudaStreamWaitEvent(s_aux1, ev_root, 0);
    cudaStreamWaitEvent(s_aux2, ev_root, 0);

    k_stats <<< 32, 1024, 0, s_aux1 >>> (vel, Kin, Wa, ba, Wm, bm, out, out_size);
    k_gmax  <<< 1024, 256, 0, s_aux1 >>> (eps);
    cudaEventRecord(ev_j1, s_aux1);

    k_center<<< dim3(NA, 8), 256, 0, s_aux2 >>> (Wc, bc);
    cudaEventRecord(ev_j2, s_aux2);

    k_mmat  <<< dim3(4, MM_KSPLIT), 288 >>> (Wc, bc);
    cudaStreamWaitEvent(0, ev_j1, 0);
    cudaStreamWaitEvent(0, ev_j2, 0);
    k_conv  <<< dim3(WSZ / 128, K3_DSPLIT), 288 >>> (eps);
    k_out_tc<<< dim3(WSZ / KO_TT, BATCH / KO_BT), 256, KO_SMEM >>> (vel, Kin, out);
}

// round 8
// speedup vs baseline: 1.7697x; 1.0003x over previous
#include <cuda_runtime.h>
#include <math.h>

#define BATCH 1024
#define WSZ   8192
#define DIN   65
#define NA    66
#define IRL   16382
#define MI_N  513
#define INV_MAXSTEPS (1.0f/2799.0f)
#define PI_OVER_8191 (3.14159265358979323846f/8191.0f)

__device__ float        g_mean[BATCH];
__device__ float        g_amps[BATCH];
__device__ unsigned int g_max_u;
__device__ float        g_D[MI_N * NA];   // windowed DCT columns [mi][i], h folded
__device__ float        g_P[NA * WSZ];    // conv result [i][t]

__device__ __forceinline__ unsigned f2tf32(float f) {
    unsigned u;
    asm("cvt.rna.tf32.f32 %0, %1;" : "=r"(u) : "f"(f));
    return u;
}
__device__ __forceinline__ float cos_ph(int p) {   // p in [0, IRL)
    int p2 = (p >= 8191) ? (p - IRL) : p;
    return __cosf((float)p2 * PI_OVER_8191);
}

// ---------------------------------------------------------------------------
__global__ void k_init() {
    int idx = blockIdx.x * blockDim.x + threadIdx.x;
    if (idx < (NA * WSZ) / 4)
        reinterpret_cast<float4*>(g_P)[idx] = make_float4(0.f, 0.f, 0.f, 0.f);
    if (idx < MI_N * NA) g_D[idx] = 0.0f;
    if (idx == 0)        g_max_u = 0u;
}

// ---------------------------------------------------------------------------
// Center column mi=512 (m=8191): cos = (-1)^k, h=1. Split-k x8 + atomicAdd.
__global__ void k_center(const float* __restrict__ Wc, const float* __restrict__ bc) {
    __shared__ float red[8];
    int i = blockIdx.x;
    int kc = blockIdx.y * 1024;
    const float* row = (i < DIN) ? &Wc[i * WSZ] : bc;
    float s = 0.0f;
    for (int k = kc + threadIdx.x; k < kc + 1024; k += 256) {
        float gk = (k == 0 || k == WSZ - 1) ? 1.0f : 2.0f;
        float sgn = (k & 1) ? -1.0f : 1.0f;
        s += row[k] * gk * sgn;
    }
    #pragma unroll
    for (int o = 16; o; o >>= 1) s += __shfl_xor_sync(0xffffffffu, s, o);
    if ((threadIdx.x & 31) == 0) red[threadIdx.x >> 5] = s;
    __syncthreads();
    if (threadIdx.x == 0) {
        float t = 0.0f;
        #pragma unroll
        for (int w = 0; w < 8; w++) t += red[w];
        atomicAdd(&g_D[512 * NA + i], t * (1.0f / 16382.0f));
    }
}

// ---------------------------------------------------------------------------
__global__ void k_stats(const float* __restrict__ vel, const float* __restrict__ Kin,
                        const float* __restrict__ Wa, const float* __restrict__ ba,
                        const float* __restrict__ Wm, const float* __restrict__ bm,
                        float* __restrict__ out, int out_size) {
    int gw = (blockIdx.x * blockDim.x + threadIdx.x) >> 5;
    int lane = threadIdx.x & 31;
    if (gw >= BATCH) return;
    float sa = 0.0f, sm = 0.0f;
    #pragma unroll
    for (int i = lane; i < 64; i += 32) {
        float x = vel[gw * 64 + i];
        sa += x * Wa[i];
        sm += x * Wm[i];
    }
    if (lane == 0) {
        float xk = Kin[gw] * INV_MAXSTEPS;
        sa += xk * Wa[64];
        sm += xk * Wm[64];
    }
    #pragma unroll
    for (int o = 16; o; o >>= 1) {
        sa += __shfl_down_sync(0xffffffffu, sa, o);
        sm += __shfl_down_sync(0xffffffffu, sm, o);
    }
    if (lane == 0) {
        float m = tanhf(sm + bm[0]);
        float a = 1.0f / (1.0f + expf(-(sa + ba[0])));
        g_mean[gw] = m;
        g_amps[gw] = a;
        if (out_size >= BATCH * WSZ + BATCH)
            out[BATCH * WSZ + gw] = m;
    }
}

// ---------------------------------------------------------------------------
__global__ void k_gmax(const float* __restrict__ eps) {
    const int N4 = (BATCH * WSZ) / 4;
    const float NEG = __int_as_float(0xff800000);
    int stride = gridDim.x * blockDim.x;
    int i0 = blockIdx.x * blockDim.x + threadIdx.x;
    const float4* e4 = reinterpret_cast<const float4*>(eps);
    float a0 = NEG, a1 = NEG, a2 = NEG, a3 = NEG;
    for (int j = i0; j < N4; j += 4 * stride) {
        int j1 = j + stride, j2 = j + 2 * stride, j3 = j + 3 * stride;
        float4 v0 = e4[j];
        float4 v1 = (j1 < N4) ? e4[j1] : make_float4(NEG,NEG,NEG,NEG);
        float4 v2 = (j2 < N4) ? e4[j2] : make_float4(NEG,NEG,NEG,NEG);
        float4 v3 = (j3 < N4) ? e4[j3] : make_float4(NEG,NEG,NEG,NEG);
        float m0 = g_mean[j >> 11];
        float m1 = (j1 < N4) ? g_mean[j1 >> 11] : 0.0f;
        float m2 = (j2 < N4) ? g_mean[j2 >> 11] : 0.0f;
        float m3 = (j3 < N4) ? g_mean[j3 >> 11] : 0.0f;
        a0 = fmaxf(a0, m0 + fmaxf(fmaxf(v0.x, v0.y), fmaxf(v0.z, v0.w)));
        a1 = fmaxf(a1, m1 + fmaxf(fmaxf(v1.x, v1.y), fmaxf(v1.z, v1.w)));
        a2 = fmaxf(a2, m2 + fmaxf(fmaxf(v2.x, v2.y), fmaxf(v2.z, v2.w)));
        a3 = fmaxf(a3, m3 + fmaxf(fmaxf(v3.x, v3.y), fmaxf(v3.z, v3.w)));
    }
    float lm = fmaxf(fmaxf(a0, a1), fmaxf(a2, a3));
    #pragma unroll
    for (int o = 16; o; o >>= 1)
        lm = fmaxf(lm, __shfl_xor_sync(0xffffffffu, lm, o));
    if ((threadIdx.x & 31) == 0) {
        unsigned b = __float_as_uint(lm);
        unsigned enc = (b & 0x80000000u) ? ~b : (b | 0x80000000u);
        atomicMax(&g_max_u, enc);
    }
}

// ---------------------------------------------------------------------------
// Double-folded DCT with Chebyshev cosine recurrence (proven R7 WIN).
#define MM_KSPLIT 64
#define MM_SUB 32
__global__ void __launch_bounds__(288) k_mmat(const float* __restrict__ Wc,
                                              const float* __restrict__ bc) {
    __shared__ float sWe[MM_SUB * 76];
    __shared__ float sWo[MM_SUB * 76];
    __shared__ float sC[MM_SUB * 128];
    int tid = threadIdx.x;
    int tx = tid & 31;
    int iy = tid >> 5;
    int mi0 = blockIdx.x * 128;
    int k0  = blockIdx.y * 64;

    int mfill = tid & 127;
    int half  = (tid >> 7) & 1;
    float x0 = 0.f, x1 = 0.f, tc = 0.f;
    if (tid < 256) {
        int mmf = 7679 + mi0 + mfill;
        int stepk = 2 * mmf; if (stepk >= IRL) stepk -= IRL;
        int ph0 = (int)(((long long)(k0 + half) * (long long)mmf) % IRL);
        int ph1 = ph0 + stepk; if (ph1 >= IRL) ph1 -= IRL;
        x0 = cos_ph(ph0);
        x1 = cos_ph(ph1);
        tc = 2.0f * cos_ph(stepk);
    }

    float acc[8][4];
    #pragma unroll
    for (int q = 0; q < 8; q++)
        #pragma unroll
        for (int r = 0; r < 4; r++) acc[q][r] = 0.0f;

    for (int c = 0; c < 64 / MM_SUB; c++) {
        int kc = k0 + c * MM_SUB;
        __syncthreads();
        for (int idx = tid; idx < 72 * MM_SUB; idx += 288) {
            int i = idx >> 5, kk = idx & 31;
            int k = kc + kk, kb = 8191 - k;
            float va = (i < DIN) ? Wc[i * WSZ + k]  : (i == DIN ? bc[k]  : 0.0f);
            float vb = (i < DIN) ? Wc[i * WSZ + kb] : (i == DIN ? bc[kb] : 0.0f);
            float ga = (k == 0) ? 1.0f : 2.0f;
            float gb = (kb == WSZ - 1) ? 1.0f : 2.0f;
            sWe[kk * 76 + i] = va * ga + vb * gb;
            sWo[kk * 76 + i] = va * ga - vb * gb;
        }
        if (tid < 256) {
            #pragma unroll
            for (int s = 0; s < 16; s++) {
                sC[(half + 2 * s) * 128 + mfill] = x0;
                float nx = fmaf(tc, x1, -x0);
                x0 = x1; x1 = nx;
            }
        }
        __syncthreads();
        #pragma unroll 8
        for (int kk = 0; kk < MM_SUB; kk++) {
            float4 cv = *reinterpret_cast<const float4*>(&sC[kk * 128 + tx * 4]);
            float4 ea = *reinterpret_cast<const float4*>(&sWe[kk * 76 + iy * 8]);
            float4 eb = *reinterpret_cast<const float4*>(&sWe[kk * 76 + iy * 8 + 4]);
            float4 oa = *reinterpret_cast<const float4*>(&sWo[kk * 76 + iy * 8]);
            float4 ob = *reinterpret_cast<const float4*>(&sWo[kk * 76 + iy * 8 + 4]);
            float ev[8] = {ea.x, ea.y, ea.z, ea.w, eb.x, eb.y, eb.z, eb.w};
            float ov[8] = {oa.x, oa.y, oa.z, oa.w, ob.x, ob.y, ob.z, ob.w};
            #pragma unroll
            for (int q = 0; q < 8; q++) {
                acc[q][0] = fmaf(ov[q], cv.x, acc[q][0]);
                acc[q][1] = fmaf(ev[q], cv.y, acc[q][1]);
                acc[q][2] = fmaf(ov[q], cv.z, acc[q][2]);
                acc[q][3] = fmaf(ev[q], cv.w, acc[q][3]);
            }
        }
    }

    #pragma unroll
    for (int r = 0; r < 4; r++) {
        int mi = mi0 + tx * 4 + r;
        int jh = (mi >= 2) ? (mi - 2) : (1022 - mi);
        float h = 0.5f - 0.5f * cospif((float)(jh + 2) * (1.0f / 512.0f));
        float sc = h * (1.0f / 16382.0f);
        #pragma unroll
        for (int q = 0; q < 8; q++) {
            int i = iy * 8 + q;
            if (i < NA)
                atomicAdd(&g_D[mi * NA + i], acc[q][r] * sc);
        }
    }
}

// ---------------------------------------------------------------------------
// Tensor-core folded FIR, v2 (proper occupancy):
//   P[i][t] = sum_dd Cf[dd][i] * F[dd][t], K = 513 taps:
//     dd 0..509: d=dd+1, Cf=D[511-dd], F=n(t+d)+n(t-d)
//     dd 510: Cf=D[512], F=n(t); dd 511: Cf=D[1], F=n(t-511)
//     dd 512: Cf=D[0], F=n(t-512); pad zero beyond.
// Grid (64 t-tiles of 128, 4 K-splits {5,4,4,4} chunks of 32). 256 thr, 8 warps.
#define FST 136
__global__ void __launch_bounds__(256) k_conv_tc2(const float* __restrict__ eps) {
    __shared__ float    sN[1152];
    __shared__ unsigned sF[32 * FST];   // [dd][t], tf32
    __shared__ unsigned sCf[32 * 72];   // [dd][i], tf32
    int tid = threadIdx.x;
    int lane = tid & 31, w = tid >> 5;
    int t0 = blockIdx.x * 128;
    int y  = blockIdx.y;
    int c0 = (y == 0) ? 0 : (5 + 4 * (y - 1));
    int c1 = c0 + ((y == 0) ? 5 : 4);

    float mean0 = g_mean[0];
    unsigned encm = g_max_u;
    float gmax = (encm & 0x80000000u) ? __uint_as_float(encm & 0x7fffffffu)
                                      : __uint_as_float(~encm);
    float inv = 1.0f / gmax;
    for (int s = tid; s < 1152; s += 256) {
        int u = t0 - 512 + s;
        sN[s] = (u >= 0 && u < WSZ) ? (mean0 + eps[u]) * inv : 0.0f;
    }

    int r = lane >> 2, cq = lane & 3;
    int tw = w * 16;
    float acc[9][4];
    #pragma unroll
    for (int nf = 0; nf < 9; nf++)
        #pragma unroll
        for (int q = 0; q < 4; q++) acc[nf][q] = 0.0f;

    for (int c = c0; c < c1; c++) {
        int dd0 = 32 * c;
        __syncthreads();
        for (int idx = tid; idx < 32 * 128; idx += 256) {
            int ddl = idx >> 7, tt = idx & 127;
            int dd = dd0 + ddl;
            int x = 512 + tt;
            float f;
            if (dd < 510)       { int d = dd + 1; f = sN[x + d] + sN[x - d]; }
            else if (dd == 510) f = sN[x];
            else if (dd == 511) f = sN[x - 511];
            else if (dd == 512) f = sN[x - 512];
            else                f = 0.0f;
            sF[ddl * FST + tt] = f2tf32(f);
        }
        for (int idx = tid; idx < 32 * 72; idx += 256) {
            int ddl = idx / 72, i = idx % 72;
            int dd = dd0 + ddl;
            int mi;
            if (dd < 510)       mi = 511 - dd;
            else if (dd == 510) mi = 512;
            else if (dd == 511) mi = 1;
            else if (dd == 512) mi = 0;
            else                mi = -1;
            float v = (mi >= 0 && i < NA) ? g_D[mi * NA + i] : 0.0f;
            sCf[ddl * 72 + i] = f2tf32(v);
        }
        __syncthreads();
        #pragma unroll
        for (int ks = 0; ks < 4; ks++) {
            int k0 = ks * 8;
            unsigned a0 = sF[(k0 + cq) * FST + tw + r];
            unsigned a1 = sF[(k0 + cq) * FST + tw + r + 8];
            unsigned a2 = sF[(k0 + cq + 4) * FST + tw + r];
            unsigned a3 = sF[(k0 + cq + 4) * FST + tw + r + 8];
            #pragma unroll
            for (int nf = 0; nf < 9; nf++) {
                unsigned b0 = sCf[(k0 + cq) * 72 + nf * 8 + r];
                unsigned b1 = sCf[(k0 + cq + 4) * 72 + nf * 8 + r];
                asm volatile(
                    "mma.sync.aligned.m16n8k8.row.col.f32.tf32.tf32.f32 "
                    "{%0,%1,%2,%3}, {%4,%5,%6,%7}, {%8,%9}, {%0,%1,%2,%3};"
                    : "+f"(acc[nf][0]), "+f"(acc[nf][1]),
                      "+f"(acc[nf][2]), "+f"(acc[nf][3])
                    : "r"(a0), "r"(a1), "r"(a2), "r"(a3),
                      "r"(b0), "r"(b1));
            }
        }
    }

    int t = t0 + tw + r;
    #pragma unroll
    for (int nf = 0; nf < 9; nf++) {
        int i0 = nf * 8 + 2 * cq;
        if (i0 < NA) {
            atomicAdd(&g_P[i0 * WSZ + t],     acc[nf][0]);
            atomicAdd(&g_P[i0 * WSZ + t + 8], acc[nf][2]);
        }
        if (i0 + 1 < NA) {
            atomicAdd(&g_P[(i0 + 1) * WSZ + t],     acc[nf][1]);
            atomicAdd(&g_P[(i0 + 1) * WSZ + t + 8], acc[nf][3]);
        }
    }
}

// ---------------------------------------------------------------------------
// k_out via tf32 mma (unchanged).
#define KO_BT 64
#define KO_TT 128
#define KO_K  72
#define PST 136
#define XST 76
#define KO_SMEM ((KO_K * PST + KO_BT * XST) * 4 + KO_BT * 4)

extern __shared__ unsigned ko_smem[];
__global__ void __launch_bounds__(256) k_out_tc(const float* __restrict__ vel,
                                                const float* __restrict__ Kin,
                                                float* __restrict__ out) {
    unsigned* sP = ko_smem;
    unsigned* sX = ko_smem + KO_K * PST;
    float*    sA = (float*)(sX + KO_BT * XST);
    int tid = threadIdx.x, lane = tid & 31, w = tid >> 5;
    int t0 = blockIdx.x * KO_TT, b0 = blockIdx.y * KO_BT;

    for (int idx = tid; idx < KO_K * KO_TT; idx += 256) {
        int i = idx >> 7, tt = idx & 127;
        float v = (i < NA) ? g_P[i * WSZ + t0 + tt] : 0.0f;
        sP[i * PST + tt] = f2tf32(v);
    }
    for (int idx = tid; idx < KO_BT * KO_K; idx += 256) {
        int bb = idx / KO_K, i = idx % KO_K;
        int b = b0 + bb;
        float x;
        if (i < 64)       x = vel[b * 64 + i];
        else if (i == 64) x = Kin[b] * INV_MAXSTEPS;
        else if (i == 65) x = 1.0f;
        else              x = 0.0f;
        sX[bb * XST + i] = f2tf32(x);
    }
    if (tid < KO_BT) sA[tid] = g_amps[b0 + tid];
    __syncthreads();

    int wb = w & 1, wt = w >> 1;
    int r = lane >> 2, cq = lane & 3;
    float c[2][4][4];
    #pragma unroll
    for (int mf = 0; mf < 2; mf++)
        #pragma unroll
        for (int nf = 0; nf < 4; nf++)
            #pragma unroll
            for (int q = 0; q < 4; q++) c[mf][nf][q] = 0.0f;

    #pragma unroll
    for (int s = 0; s < KO_K / 8; s++) {
        int k0 = s * 8;
        unsigned a[2][4];
        #pragma unroll
        for (int mf = 0; mf < 2; mf++) {
            int rb = wb * 32 + mf * 16 + r;
            a[mf][0] = sX[rb * XST + k0 + cq];
            a[mf][1] = sX[(rb + 8) * XST + k0 + cq];
            a[mf][2] = sX[rb * XST + k0 + cq + 4];
            a[mf][3] = sX[(rb + 8) * XST + k0 + cq + 4];
        }
        unsigned bf[4][2];
        #pragma unroll
        for (int nf = 0; nf < 4; nf++) {
            int ct = wt * 32 + nf * 8 + r;
            bf[nf][0] = sP[(k0 + cq) * PST + ct];
            bf[nf][1] = sP[(k0 + cq + 4) * PST + ct];
        }
        #pragma unroll
        for (int mf = 0; mf < 2; mf++)
            #pragma unroll
            for (int nf = 0; nf < 4; nf++) {
                asm volatile(
                    "mma.sync.aligned.m16n8k8.row.col.f32.tf32.tf32.f32 "
                    "{%0,%1,%2,%3}, {%4,%5,%6,%7}, {%8,%9}, {%0,%1,%2,%3};"
                    : "+f"(c[mf][nf][0]), "+f"(c[mf][nf][1]),
                      "+f"(c[mf][nf][2]), "+f"(c[mf][nf][3])
                    : "r"(a[mf][0]), "r"(a[mf][1]), "r"(a[mf][2]), "r"(a[mf][3]),
                      "r"(bf[nf][0]), "r"(bf[nf][1]));
            }
    }

    #pragma unroll
    for (int mf = 0; mf < 2; mf++) {
        int rbl = wb * 32 + mf * 16 + r;
        float a1 = sA[rbl], a2 = sA[rbl + 8];
        int rb = b0 + rbl;
        #pragma unroll
        for (int nf = 0; nf < 4; nf++) {
            int ct = t0 + wt * 32 + nf * 8 + 2 * cq;
            float2 o1 = make_float2(a1 * c[mf][nf][0], a1 * c[mf][nf][1]);
            float2 o2 = make_float2(a2 * c[mf][nf][2], a2 * c[mf][nf][3]);
            *reinterpret_cast<float2*>(&out[rb * WSZ + ct])       = o1;
            *reinterpret_cast<float2*>(&out[(rb + 8) * WSZ + ct]) = o2;
        }
    }
}

// ---------------------------------------------------------------------------
static cudaStream_t s_aux1, s_aux2;
static cudaEvent_t  ev_root, ev_j1, ev_j2;
namespace {
struct StreamBoot {
    StreamBoot() {
        cudaStreamCreateWithFlags(&s_aux1, cudaStreamNonBlocking);
        cudaStreamCreateWithFlags(&s_aux2, cudaStreamNonBlocking);
        cudaEventCreateWithFlags(&ev_root, cudaEventDisableTiming);
        cudaEventCreateWithFlags(&ev_j1,   cudaEventDisableTiming);
        cudaEventCreateWithFlags(&ev_j2,   cudaEventDisableTiming);
    }
};
static StreamBoot g_stream_boot;
}

extern "C" void kernel_launch(void* const* d_in, const int* in_sizes, int n_in,
                              void* d_out, int out_size) {
    const float* vel = (const float*)d_in[0];
    const float* Kin = (const float*)d_in[1];
    const float* eps = (const float*)d_in[2];
    const float* Wc  = (const float*)d_in[3];
    const float* bc  = (const float*)d_in[4];
    const float* Wa  = (const float*)d_in[5];
    const float* ba  = (const float*)d_in[6];
    const float* Wm  = (const float*)d_in[7];
    const float* bm  = (const float*)d_in[8];
    float* out = (float*)d_out;

    cudaFuncSetAttribute(k_out_tc, cudaFuncAttributeMaxDynamicSharedMemorySize, KO_SMEM);

    k_init  <<< (NA * WSZ / 4 + 255) / 256, 256 >>> ();
    cudaEventRecord(ev_root, 0);
    cudaStreamWaitEvent(s_aux1, ev_root, 0);
    cudaStreamWaitEvent(s_aux2, ev_root, 0);

    k_stats <<< 32, 1024, 0, s_aux1 >>> (vel, Kin, Wa, ba, Wm, bm, out, out_size);
    k_gmax  <<< 1024, 256, 0, s_aux1 >>> (eps);
    cudaEventRecord(ev_j1, s_aux1);

    k_center<<< dim3(NA, 8), 256, 0, s_aux2 >>> (Wc, bc);
    cudaEventRecord(ev_j2, s_aux2);

    k_mmat  <<< dim3(4, MM_KSPLIT), 288 >>> (Wc, bc);
    cudaStreamWaitEvent(0, ev_j1, 0);
    cudaStreamWaitEvent(0, ev_j2, 0);
    k_conv_tc2<<< dim3(64, 4), 256 >>> (eps);
    k_out_tc<<< dim3(WSZ / KO_TT, BATCH / KO_BT), 256, KO_SMEM >>> (vel, Kin, out);
}

// round 9
// speedup vs baseline: 2.2325x; 1.2615x over previous
#include <cuda_runtime.h>
#include <cuda_fp16.h>
#include <math.h>

#define BATCH 1024
#define WSZ   8192
#define DIN   65
#define NA    66
#define IRL   16382
#define MI_N  513
#define INV_MAXSTEPS (1.0f/2799.0f)
#define PI_OVER_8191 (3.14159265358979323846f/8191.0f)

__device__ float        g_mean[BATCH];
__device__ float        g_amps[BATCH];
__device__ unsigned int g_max_u;
__device__ float        g_D[MI_N * NA];   // windowed DCT columns [mi][i], h folded
__device__ float        g_P[NA * WSZ];    // conv result [i][t]

__device__ __forceinline__ float cos_ph(int p) {   // p in [0, IRL)
    int p2 = (p >= 8191) ? (p - IRL) : p;
    return __cosf((float)p2 * PI_OVER_8191);
}
__device__ __forceinline__ unsigned pack_h2(float a, float b) {
    __half2 h = __floats2half2_rn(a, b);
    return *reinterpret_cast<unsigned*>(&h);
}

// ---------------------------------------------------------------------------
__global__ void k_init() {
    int idx = blockIdx.x * blockDim.x + threadIdx.x;
    if (idx < (NA * WSZ) / 4)
        reinterpret_cast<float4*>(g_P)[idx] = make_float4(0.f, 0.f, 0.f, 0.f);
    if (idx < MI_N * NA) g_D[idx] = 0.0f;
    if (idx == 0)        g_max_u = 0u;
}

// ---------------------------------------------------------------------------
// Center column mi=512 (m=8191): cos = (-1)^k, h=1. Split-k x8 + atomicAdd.
__global__ void k_center(const float* __restrict__ Wc, const float* __restrict__ bc) {
    __shared__ float red[8];
    int i = blockIdx.x;
    int kc = blockIdx.y * 1024;
    const float* row = (i < DIN) ? &Wc[i * WSZ] : bc;
    float s = 0.0f;
    for (int k = kc + threadIdx.x; k < kc + 1024; k += 256) {
        float gk = (k == 0 || k == WSZ - 1) ? 1.0f : 2.0f;
        float sgn = (k & 1) ? -1.0f : 1.0f;
        s += row[k] * gk * sgn;
    }
    #pragma unroll
    for (int o = 16; o; o >>= 1) s += __shfl_xor_sync(0xffffffffu, s, o);
    if ((threadIdx.x & 31) == 0) red[threadIdx.x >> 5] = s;
    __syncthreads();
    if (threadIdx.x == 0) {
        float t = 0.0f;
        #pragma unroll
        for (int w = 0; w < 8; w++) t += red[w];
        atomicAdd(&g_D[512 * NA + i], t * (1.0f / 16382.0f));
    }
}

// ---------------------------------------------------------------------------
__global__ void k_stats(const float* __restrict__ vel, const float* __restrict__ Kin,
                        const float* __restrict__ Wa, const float* __restrict__ ba,
                        const float* __restrict__ Wm, const float* __restrict__ bm,
                        float* __restrict__ out, int out_size) {
    int gw = (blockIdx.x * blockDim.x + threadIdx.x) >> 5;
    int lane = threadIdx.x & 31;
    if (gw >= BATCH) return;
    float sa = 0.0f, sm = 0.0f;
    #pragma unroll
    for (int i = lane; i < 64; i += 32) {
        float x = vel[gw * 64 + i];
        sa += x * Wa[i];
        sm += x * Wm[i];
    }
    if (lane == 0) {
        float xk = Kin[gw] * INV_MAXSTEPS;
        sa += xk * Wa[64];
        sm += xk * Wm[64];
    }
    #pragma unroll
    for (int o = 16; o; o >>= 1) {
        sa += __shfl_down_sync(0xffffffffu, sa, o);
        sm += __shfl_down_sync(0xffffffffu, sm, o);
    }
    if (lane == 0) {
        float m = tanhf(sm + bm[0]);
        float a = 1.0f / (1.0f + expf(-(sa + ba[0])));
        g_mean[gw] = m;
        g_amps[gw] = a;
        if (out_size >= BATCH * WSZ + BATCH)
            out[BATCH * WSZ + gw] = m;
    }
}

// ---------------------------------------------------------------------------
__global__ void k_gmax(const float* __restrict__ eps) {
    const int N4 = (BATCH * WSZ) / 4;
    const float NEG = __int_as_float(0xff800000);
    int stride = gridDim.x * blockDim.x;
    int i0 = blockIdx.x * blockDim.x + threadIdx.x;
    const float4* e4 = reinterpret_cast<const float4*>(eps);
    float a0 = NEG, a1 = NEG, a2 = NEG, a3 = NEG;
    for (int j = i0; j < N4; j += 4 * stride) {
        int j1 = j + stride, j2 = j + 2 * stride, j3 = j + 3 * stride;
        float4 v0 = e4[j];
        float4 v1 = (j1 < N4) ? e4[j1] : make_float4(NEG,NEG,NEG,NEG);
        float4 v2 = (j2 < N4) ? e4[j2] : make_float4(NEG,NEG,NEG,NEG);
        float4 v3 = (j3 < N4) ? e4[j3] : make_float4(NEG,NEG,NEG,NEG);
        float m0 = g_mean[j >> 11];
        float m1 = (j1 < N4) ? g_mean[j1 >> 11] : 0.0f;
        float m2 = (j2 < N4) ? g_mean[j2 >> 11] : 0.0f;
        float m3 = (j3 < N4) ? g_mean[j3 >> 11] : 0.0f;
        a0 = fmaxf(a0, m0 + fmaxf(fmaxf(v0.x, v0.y), fmaxf(v0.z, v0.w)));
        a1 = fmaxf(a1, m1 + fmaxf(fmaxf(v1.x, v1.y), fmaxf(v1.z, v1.w)));
        a2 = fmaxf(a2, m2 + fmaxf(fmaxf(v2.x, v2.y), fmaxf(v2.z, v2.w)));
        a3 = fmaxf(a3, m3 + fmaxf(fmaxf(v3.x, v3.y), fmaxf(v3.z, v3.w)));
    }
    float lm = fmaxf(fmaxf(a0, a1), fmaxf(a2, a3));
    #pragma unroll
    for (int o = 16; o; o >>= 1)
        lm = fmaxf(lm, __shfl_xor_sync(0xffffffffu, lm, o));
    if ((threadIdx.x & 31) == 0) {
        unsigned b = __float_as_uint(lm);
        unsigned enc = (b & 0x80000000u) ? ~b : (b | 0x80000000u);
        atomicMax(&g_max_u, enc);
    }
}

// ---------------------------------------------------------------------------
// Double-folded DCT with Chebyshev cosine recurrence (proven R7 WIN).
#define MM_KSPLIT 64
#define MM_SUB 32
__global__ void __launch_bounds__(288) k_mmat(const float* __restrict__ Wc,
                                              const float* __restrict__ bc) {
    __shared__ float sWe[MM_SUB * 76];
    __shared__ float sWo[MM_SUB * 76];
    __shared__ float sC[MM_SUB * 128];
    int tid = threadIdx.x;
    int tx = tid & 31;
    int iy = tid >> 5;
    int mi0 = blockIdx.x * 128;
    int k0  = blockIdx.y * 64;

    int mfill = tid & 127;
    int half  = (tid >> 7) & 1;
    float x0 = 0.f, x1 = 0.f, tc = 0.f;
    if (tid < 256) {
        int mmf = 7679 + mi0 + mfill;
        int stepk = 2 * mmf; if (stepk >= IRL) stepk -= IRL;
        int ph0 = (int)(((long long)(k0 + half) * (long long)mmf) % IRL);
        int ph1 = ph0 + stepk; if (ph1 >= IRL) ph1 -= IRL;
        x0 = cos_ph(ph0);
        x1 = cos_ph(ph1);
        tc = 2.0f * cos_ph(stepk);
    }

    float acc[8][4];
    #pragma unroll
    for (int q = 0; q < 8; q++)
        #pragma unroll
        for (int r = 0; r < 4; r++) acc[q][r] = 0.0f;

    for (int c = 0; c < 64 / MM_SUB; c++) {
        int kc = k0 + c * MM_SUB;
        __syncthreads();
        for (int idx = tid; idx < 72 * MM_SUB; idx += 288) {
            int i = idx >> 5, kk = idx & 31;
            int k = kc + kk, kb = 8191 - k;
            float va = (i < DIN) ? Wc[i * WSZ + k]  : (i == DIN ? bc[k]  : 0.0f);
            float vb = (i < DIN) ? Wc[i * WSZ + kb] : (i == DIN ? bc[kb] : 0.0f);
            float ga = (k == 0) ? 1.0f : 2.0f;
            float gb = (kb == WSZ - 1) ? 1.0f : 2.0f;
            sWe[kk * 76 + i] = va * ga + vb * gb;
            sWo[kk * 76 + i] = va * ga - vb * gb;
        }
        if (tid < 256) {
            #pragma unroll
            for (int s = 0; s < 16; s++) {
                sC[(half + 2 * s) * 128 + mfill] = x0;
                float nx = fmaf(tc, x1, -x0);
                x0 = x1; x1 = nx;
            }
        }
        __syncthreads();
        #pragma unroll 8
        for (int kk = 0; kk < MM_SUB; kk++) {
            float4 cv = *reinterpret_cast<const float4*>(&sC[kk * 128 + tx * 4]);
            float4 ea = *reinterpret_cast<const float4*>(&sWe[kk * 76 + iy * 8]);
            float4 eb = *reinterpret_cast<const float4*>(&sWe[kk * 76 + iy * 8 + 4]);
            float4 oa = *reinterpret_cast<const float4*>(&sWo[kk * 76 + iy * 8]);
            float4 ob = *reinterpret_cast<const float4*>(&sWo[kk * 76 + iy * 8 + 4]);
            float ev[8] = {ea.x, ea.y, ea.z, ea.w, eb.x, eb.y, eb.z, eb.w};
            float ov[8] = {oa.x, oa.y, oa.z, oa.w, ob.x, ob.y, ob.z, ob.w};
            #pragma unroll
            for (int q = 0; q < 8; q++) {
                acc[q][0] = fmaf(ov[q], cv.x, acc[q][0]);
                acc[q][1] = fmaf(ev[q], cv.y, acc[q][1]);
                acc[q][2] = fmaf(ov[q], cv.z, acc[q][2]);
                acc[q][3] = fmaf(ev[q], cv.w, acc[q][3]);
            }
        }
    }

    #pragma unroll
    for (int r = 0; r < 4; r++) {
        int mi = mi0 + tx * 4 + r;
        int jh = (mi >= 2) ? (mi - 2) : (1022 - mi);
        float h = 0.5f - 0.5f * cospif((float)(jh + 2) * (1.0f / 512.0f));
        float sc = h * (1.0f / 16382.0f);
        #pragma unroll
        for (int q = 0; q < 8; q++) {
            int i = iy * 8 + q;
            if (i < NA)
                atomicAdd(&g_D[mi * NA + i], acc[q][r] * sc);
        }
    }
}

// ---------------------------------------------------------------------------
// Tensor-core folded FIR, fp16 m16n8k16 (fp32 accumulate):
//   P[i][t] = sum_dd Cf[dd][i] * F[dd][t], K=513 taps padded to 544.
// Grid (64 t-tiles of 128, 4 K-splits {5,4,4,4} chunks of 32 dd). 256 thr.
#define FSTH 136
__global__ void __launch_bounds__(256) k_conv_tc2(const float* __restrict__ eps) {
    __shared__ float    sN[1152];
    __shared__ unsigned sF[16 * FSTH];   // [khalf][t], half2 over dd-pair
    __shared__ unsigned sCf[16 * 72];    // [khalf][i]
    int tid = threadIdx.x;
    int lane = tid & 31, w = tid >> 5;
    int t0 = blockIdx.x * 128;
    int y  = blockIdx.y;
    int c0 = (y == 0) ? 0 : (5 + 4 * (y - 1));
    int c1 = c0 + ((y == 0) ? 5 : 4);

    float mean0 = g_mean[0];
    unsigned encm = g_max_u;
    float gmax = (encm & 0x80000000u) ? __uint_as_float(encm & 0x7fffffffu)
                                      : __uint_as_float(~encm);
    float inv = 1.0f / gmax;
    for (int s = tid; s < 1152; s += 256) {
        int u = t0 - 512 + s;
        sN[s] = (u >= 0 && u < WSZ) ? (mean0 + eps[u]) * inv : 0.0f;
    }

    int r = lane >> 2, cq = lane & 3;
    int tw = w * 16;
    float acc[9][4];
    #pragma unroll
    for (int nf = 0; nf < 9; nf++)
        #pragma unroll
        for (int q = 0; q < 4; q++) acc[nf][q] = 0.0f;

    for (int c = c0; c < c1; c++) {
        int dd0 = 32 * c;
        __syncthreads();
        // F tile: 16 khalf x 128 t, each packs dd pair (dd0+2kh, dd0+2kh+1)
        for (int idx = tid; idx < 16 * 128; idx += 256) {
            int kh = idx >> 7, tt = idx & 127;
            int x = 512 + tt;
            float f[2];
            #pragma unroll
            for (int p = 0; p < 2; p++) {
                int dd = dd0 + 2 * kh + p;
                float v;
                if (dd < 510)       { int d = dd + 1; v = sN[x + d] + sN[x - d]; }
                else if (dd == 510) v = sN[x];
                else if (dd == 511) v = sN[x - 511];
                else if (dd == 512) v = sN[x - 512];
                else                v = 0.0f;
                f[p] = v;
            }
            sF[kh * FSTH + tt] = pack_h2(f[0], f[1]);
        }
        // Cf tile: 16 khalf x 72 i
        for (int idx = tid; idx < 16 * 72; idx += 256) {
            int kh = idx / 72, i = idx % 72;
            float d[2];
            #pragma unroll
            for (int p = 0; p < 2; p++) {
                int dd = dd0 + 2 * kh + p;
                int mi;
                if (dd < 510)       mi = 511 - dd;
                else if (dd == 510) mi = 512;
                else if (dd == 511) mi = 1;
                else if (dd == 512) mi = 0;
                else                mi = -1;
                d[p] = (mi >= 0 && i < NA) ? g_D[mi * NA + i] : 0.0f;
            }
            sCf[kh * 72 + i] = pack_h2(d[0], d[1]);
        }
        __syncthreads();
        #pragma unroll
        for (int ks = 0; ks < 2; ks++) {
            int kh = ks * 8;
            unsigned a0 = sF[(kh + cq) * FSTH + tw + r];
            unsigned a1 = sF[(kh + cq) * FSTH + tw + r + 8];
            unsigned a2 = sF[(kh + cq + 4) * FSTH + tw + r];
            unsigned a3 = sF[(kh + cq + 4) * FSTH + tw + r + 8];
            #pragma unroll
            for (int nf = 0; nf < 9; nf++) {
                unsigned b0 = sCf[(kh + cq) * 72 + nf * 8 + r];
                unsigned b1 = sCf[(kh + cq + 4) * 72 + nf * 8 + r];
                asm volatile(
                    "mma.sync.aligned.m16n8k16.row.col.f32.f16.f16.f32 "
                    "{%0,%1,%2,%3}, {%4,%5,%6,%7}, {%8,%9}, {%0,%1,%2,%3};"
                    : "+f"(acc[nf][0]), "+f"(acc[nf][1]),
                      "+f"(acc[nf][2]), "+f"(acc[nf][3])
                    : "r"(a0), "r"(a1), "r"(a2), "r"(a3),
                      "r"(b0), "r"(b1));
            }
        }
    }

    int t = t0 + tw + r;
    #pragma unroll
    for (int nf = 0; nf < 9; nf++) {
        int i0 = nf * 8 + 2 * cq;
        if (i0 < NA) {
            atomicAdd(&g_P[i0 * WSZ + t],     acc[nf][0]);
            atomicAdd(&g_P[i0 * WSZ + t + 8], acc[nf][2]);
        }
        if (i0 + 1 < NA) {
            atomicAdd(&g_P[(i0 + 1) * WSZ + t],     acc[nf][1]);
            atomicAdd(&g_P[(i0 + 1) * WSZ + t + 8], acc[nf][3]);
        }
    }
}

// ---------------------------------------------------------------------------
// k_out via fp16 m16n8k16 (fp32 accumulate). K=66 padded to 80 (40 khalf).
#define KO_TT 128
#define KO_KH 40
#define PSTH 136
#define XSTH 44
__global__ void __launch_bounds__(256) k_out_tc(const float* __restrict__ vel,
                                                const float* __restrict__ Kin,
                                                float* __restrict__ out) {
    __shared__ unsigned sP[KO_KH * PSTH];  // [khalf][t]
    __shared__ unsigned sX[64 * XSTH];     // [b][khalf]
    __shared__ float    sA[64];
    int tid = threadIdx.x, lane = tid & 31, w = tid >> 5;
    int t0 = blockIdx.x * KO_TT, b0 = blockIdx.y * 64;

    for (int idx = tid; idx < KO_KH * KO_TT; idx += 256) {
        int kh = idx >> 7, tt = idx & 127;
        int i0 = 2 * kh;
        float v0 = (i0     < NA) ? g_P[i0 * WSZ + t0 + tt]       : 0.0f;
        float v1 = (i0 + 1 < NA) ? g_P[(i0 + 1) * WSZ + t0 + tt] : 0.0f;
        sP[kh * PSTH + tt] = pack_h2(v0, v1);
    }
    for (int idx = tid; idx < 64 * KO_KH; idx += 256) {
        int bb = idx / KO_KH, kh = idx % KO_KH;
        int b = b0 + bb;
        float x[2];
        #pragma unroll
        for (int p = 0; p < 2; p++) {
            int i = 2 * kh + p;
            if (i < 64)       x[p] = vel[b * 64 + i];
            else if (i == 64) x[p] = Kin[b] * INV_MAXSTEPS;
            else if (i == 65) x[p] = 1.0f;
            else              x[p] = 0.0f;
        }
        sX[bb * XSTH + kh] = pack_h2(x[0], x[1]);
    }
    if (tid < 64) sA[tid] = g_amps[b0 + tid];
    __syncthreads();

    int wb = w & 1, wt = w >> 1;
    int r = lane >> 2, cq = lane & 3;
    float c[2][4][4];
    #pragma unroll
    for (int mf = 0; mf < 2; mf++)
        #pragma unroll
        for (int nf = 0; nf < 4; nf++)
            #pragma unroll
            for (int q = 0; q < 4; q++) c[mf][nf][q] = 0.0f;

    #pragma unroll
    for (int s = 0; s < KO_KH / 8; s++) {
        int kh = s * 8;
        unsigned a[2][4];
        #pragma unroll
        for (int mf = 0; mf < 2; mf++) {
            int rb = wb * 32 + mf * 16 + r;
            a[mf][0] = sX[rb * XSTH + kh + cq];
            a[mf][1] = sX[(rb + 8) * XSTH + kh + cq];
            a[mf][2] = sX[rb * XSTH + kh + cq + 4];
            a[mf][3] = sX[(rb + 8) * XSTH + kh + cq + 4];
        }
        unsigned bf[4][2];
        #pragma unroll
        for (int nf = 0; nf < 4; nf++) {
            int ct = wt * 32 + nf * 8 + r;
            bf[nf][0] = sP[(kh + cq) * PSTH + ct];
            bf[nf][1] = sP[(kh + cq + 4) * PSTH + ct];
        }
        #pragma unroll
        for (int mf = 0; mf < 2; mf++)
            #pragma unroll
            for (int nf = 0; nf < 4; nf++) {
                asm volatile(
                    "mma.sync.aligned.m16n8k16.row.col.f32.f16.f16.f32 "
                    "{%0,%1,%2,%3}, {%4,%5,%6,%7}, {%8,%9}, {%0,%1,%2,%3};"
                    : "+f"(c[mf][nf][0]), "+f"(c[mf][nf][1]),
                      "+f"(c[mf][nf][2]), "+f"(c[mf][nf][3])
                    : "r"(a[mf][0]), "r"(a[mf][1]), "r"(a[mf][2]), "r"(a[mf][3]),
                      "r"(bf[nf][0]), "r"(bf[nf][1]));
            }
    }

    #pragma unroll
    for (int mf = 0; mf < 2; mf++) {
        int rbl = wb * 32 + mf * 16 + r;
        float a1 = sA[rbl], a2 = sA[rbl + 8];
        int rb = b0 + rbl;
        #pragma unroll
        for (int nf = 0; nf < 4; nf++) {
            int ct = t0 + wt * 32 + nf * 8 + 2 * cq;
            float2 o1 = make_float2(a1 * c[mf][nf][0], a1 * c[mf][nf][1]);
            float2 o2 = make_float2(a2 * c[mf][nf][2], a2 * c[mf][nf][3]);
            *reinterpret_cast<float2*>(&out[rb * WSZ + ct])       = o1;
            *reinterpret_cast<float2*>(&out[(rb + 8) * WSZ + ct]) = o2;
        }
    }
}

// ---------------------------------------------------------------------------
static cudaStream_t s_aux1, s_aux2;
static cudaEvent_t  ev_root, ev_j1, ev_j2;
namespace {
struct StreamBoot {
    StreamBoot() {
        cudaStreamCreateWithFlags(&s_aux1, cudaStreamNonBlocking);
        cudaStreamCreateWithFlags(&s_aux2, cudaStreamNonBlocking);
        cudaEventCreateWithFlags(&ev_root, cudaEventDisableTiming);
        cudaEventCreateWithFlags(&ev_j1,   cudaEventDisableTiming);
        cudaEventCreateWithFlags(&ev_j2,   cudaEventDisableTiming);
    }
};
static StreamBoot g_stream_boot;
}

extern "C" void kernel_launch(void* const* d_in, const int* in_sizes, int n_in,
                              void* d_out, int out_size) {
    const float* vel = (const float*)d_in[0];
    const float* Kin = (const float*)d_in[1];
    const float* eps = (const float*)d_in[2];
    const float* Wc  = (const float*)d_in[3];
    const float* bc  = (const float*)d_in[4];
    const float* Wa  = (const float*)d_in[5];
    const float* ba  = (const float*)d_in[6];
    const float* Wm  = (const float*)d_in[7];
    const float* bm  = (const float*)d_in[8];
    float* out = (float*)d_out;

    // Submission order chosen so ncu (-s 5 -c 1, 2 harness pre-launches)
    // captures k_mmat: init, stats, gmax, mmat, center, conv, out.
    k_init  <<< (NA * WSZ / 4 + 255) / 256, 256 >>> ();
    cudaEventRecord(ev_root, 0);
    cudaStreamWaitEvent(s_aux1, ev_root, 0);
    cudaStreamWaitEvent(s_aux2, ev_root, 0);

    k_stats <<< 32, 1024, 0, s_aux1 >>> (vel, Kin, Wa, ba, Wm, bm, out, out_size);
    k_gmax  <<< 1024, 256, 0, s_aux1 >>> (eps);
    cudaEventRecord(ev_j1, s_aux1);

    k_mmat  <<< dim3(4, MM_KSPLIT), 288 >>> (Wc, bc);

    k_center<<< dim3(NA, 8), 256, 0, s_aux2 >>> (Wc, bc);
    cudaEventRecord(ev_j2, s_aux2);

    cudaStreamWaitEvent(0, ev_j1, 0);
    cudaStreamWaitEvent(0, ev_j2, 0);
    k_conv_tc2<<< dim3(64, 4), 256 >>> (eps);
    k_out_tc<<< dim3(WSZ / KO_TT, BATCH / 64), 256 >>> (vel, Kin, out);
}

// round 10
// speedup vs baseline: 2.2454x; 1.0058x over previous
#include <cuda_runtime.h>
#include <cuda_fp16.h>
#include <math.h>

#define BATCH 1024
#define WSZ   8192
#define DIN   65
#define NA    66
#define IRL   16382
#define MI_N  513
#define INV_MAXSTEPS (1.0f/2799.0f)
#define PI_OVER_8191 (3.14159265358979323846f/8191.0f)

__device__ float        g_mean[BATCH];
__device__ float        g_amps[BATCH];
__device__ unsigned int g_max_u;
__device__ float        g_D[MI_N * NA];   // windowed DCT columns [mi][i], h folded
__device__ float        g_P[NA * WSZ];    // conv result [i][t]

__device__ __forceinline__ float cos_ph(int p) {   // p in [0, IRL)
    int p2 = (p >= 8191) ? (p - IRL) : p;
    return __cosf((float)p2 * PI_OVER_8191);
}
__device__ __forceinline__ unsigned pack_h2(float a, float b) {
    __half2 h = __floats2half2_rn(a, b);
    return *reinterpret_cast<unsigned*>(&h);
}
__device__ __forceinline__ unsigned pack_hh(__half a, __half b) {
    __half2 h = __halves2half2(a, b);
    return *reinterpret_cast<unsigned*>(&h);
}

#define HMMA16(C, A0, A1, A2, A3, B0, B1)                                   \
    asm volatile(                                                           \
        "mma.sync.aligned.m16n8k16.row.col.f32.f16.f16.f32 "                \
        "{%0,%1,%2,%3}, {%4,%5,%6,%7}, {%8,%9}, {%0,%1,%2,%3};"             \
        : "+f"((C)[0]), "+f"((C)[1]), "+f"((C)[2]), "+f"((C)[3])            \
        : "r"(A0), "r"(A1), "r"(A2), "r"(A3), "r"(B0), "r"(B1))

// ---------------------------------------------------------------------------
__global__ void k_init() {
    int idx = blockIdx.x * blockDim.x + threadIdx.x;
    if (idx < (NA * WSZ) / 4)
        reinterpret_cast<float4*>(g_P)[idx] = make_float4(0.f, 0.f, 0.f, 0.f);
    if (idx < MI_N * NA) g_D[idx] = 0.0f;
    if (idx == 0)        g_max_u = 0u;
}

// ---------------------------------------------------------------------------
// Center column mi=512 (m=8191): cos = (-1)^k, h=1. Split-k x8 + atomicAdd.
__global__ void k_center(const float* __restrict__ Wc, const float* __restrict__ bc) {
    __shared__ float red[8];
    int i = blockIdx.x;
    int kc = blockIdx.y * 1024;
    const float* row = (i < DIN) ? &Wc[i * WSZ] : bc;
    float s = 0.0f;
    for (int k = kc + threadIdx.x; k < kc + 1024; k += 256) {
        float gk = (k == 0 || k == WSZ - 1) ? 1.0f : 2.0f;
        float sgn = (k & 1) ? -1.0f : 1.0f;
        s += row[k] * gk * sgn;
    }
    #pragma unroll
    for (int o = 16; o; o >>= 1) s += __shfl_xor_sync(0xffffffffu, s, o);
    if ((threadIdx.x & 31) == 0) red[threadIdx.x >> 5] = s;
    __syncthreads();
    if (threadIdx.x == 0) {
        float t = 0.0f;
        #pragma unroll
        for (int w = 0; w < 8; w++) t += red[w];
        atomicAdd(&g_D[512 * NA + i], t * (1.0f / 16382.0f));
    }
}

// ---------------------------------------------------------------------------
__global__ void k_stats(const float* __restrict__ vel, const float* __restrict__ Kin,
                        const float* __restrict__ Wa, const float* __restrict__ ba,
                        const float* __restrict__ Wm, const float* __restrict__ bm,
                        float* __restrict__ out, int out_size) {
    int gw = (blockIdx.x * blockDim.x + threadIdx.x) >> 5;
    int lane = threadIdx.x & 31;
    if (gw >= BATCH) return;
    float sa = 0.0f, sm = 0.0f;
    #pragma unroll
    for (int i = lane; i < 64; i += 32) {
        float x = vel[gw * 64 + i];
        sa += x * Wa[i];
        sm += x * Wm[i];
    }
    if (lane == 0) {
        float xk = Kin[gw] * INV_MAXSTEPS;
        sa += xk * Wa[64];
        sm += xk * Wm[64];
    }
    #pragma unroll
    for (int o = 16; o; o >>= 1) {
        sa += __shfl_down_sync(0xffffffffu, sa, o);
        sm += __shfl_down_sync(0xffffffffu, sm, o);
    }
    if (lane == 0) {
        float m = tanhf(sm + bm[0]);
        float a = 1.0f / (1.0f + expf(-(sa + ba[0])));
        g_mean[gw] = m;
        g_amps[gw] = a;
        if (out_size >= BATCH * WSZ + BATCH)
            out[BATCH * WSZ + gw] = m;
    }
}

// ---------------------------------------------------------------------------
__global__ void k_gmax(const float* __restrict__ eps) {
    const int N4 = (BATCH * WSZ) / 4;
    const float NEG = __int_as_float(0xff800000);
    int stride = gridDim.x * blockDim.x;
    int i0 = blockIdx.x * blockDim.x + threadIdx.x;
    const float4* e4 = reinterpret_cast<const float4*>(eps);
    float a0 = NEG, a1 = NEG, a2 = NEG, a3 = NEG;
    for (int j = i0; j < N4; j += 4 * stride) {
        int j1 = j + stride, j2 = j + 2 * stride, j3 = j + 3 * stride;
        float4 v0 = e4[j];
        float4 v1 = (j1 < N4) ? e4[j1] : make_float4(NEG,NEG,NEG,NEG);
        float4 v2 = (j2 < N4) ? e4[j2] : make_float4(NEG,NEG,NEG,NEG);
        float4 v3 = (j3 < N4) ? e4[j3] : make_float4(NEG,NEG,NEG,NEG);
        float m0 = g_mean[j >> 11];
        float m1 = (j1 < N4) ? g_mean[j1 >> 11] : 0.0f;
        float m2 = (j2 < N4) ? g_mean[j2 >> 11] : 0.0f;
        float m3 = (j3 < N4) ? g_mean[j3 >> 11] : 0.0f;
        a0 = fmaxf(a0, m0 + fmaxf(fmaxf(v0.x, v0.y), fmaxf(v0.z, v0.w)));
        a1 = fmaxf(a1, m1 + fmaxf(fmaxf(v1.x, v1.y), fmaxf(v1.z, v1.w)));
        a2 = fmaxf(a2, m2 + fmaxf(fmaxf(v2.x, v2.y), fmaxf(v2.z, v2.w)));
        a3 = fmaxf(a3, m3 + fmaxf(fmaxf(v3.x, v3.y), fmaxf(v3.z, v3.w)));
    }
    float lm = fmaxf(fmaxf(a0, a1), fmaxf(a2, a3));
    #pragma unroll
    for (int o = 16; o; o >>= 1)
        lm = fmaxf(lm, __shfl_xor_sync(0xffffffffu, lm, o));
    if ((threadIdx.x & 31) == 0) {
        unsigned b = __float_as_uint(lm);
        unsigned enc = (b & 0x80000000u) ? ~b : (b | 0x80000000u);
        atomicMax(&g_max_u, enc);
    }
}

// ---------------------------------------------------------------------------
// Tensor-core DCT (un-k-folded, K=8192) with split-fp16 exact precision:
//   D[mi][i] = h/16382 * sum_k gk*W[i][k]*cos(2*pi*k*(7679+mi)/16382)
// cos = ch + cl, W = wh + wl (fp16 splits); D ~= ch*wh + ch*wl + cl*wh (fp32 acc).
// Tile: 64 mi x 80 i (pad). Grid (8 mi-tiles, 64 k-splits of 128). 256 thr.
#define MMT_KSPLIT 64
__global__ void __launch_bounds__(256) k_mmat_tc(const float* __restrict__ Wc,
                                                 const float* __restrict__ bc) {
    __shared__ uint2 sC[32][68];   // [kh][mi]: (hi-pair, lo-pair) of cos(k),cos(k+1)
    __shared__ uint2 sW[32][84];   // [kh][i]:  (hi-pair, lo-pair) of gW(k),gW(k+1)
    int tid = threadIdx.x, lane = tid & 31, w = tid >> 5;
    int mi0 = blockIdx.x * 64;
    int k0  = blockIdx.y * 128;
    int r = lane >> 2, cq = lane & 3;
    int mf = w & 3, ng = w >> 2;
    int tw = mf * 16;

    // cosine-generator ownership: mi_l = tid&63, k-quarter q = tid>>6
    int mi_l = tid & 63, q = tid >> 6;
    int m = 7679 + mi0 + mi_l;            // < IRL
    float tc2 = 2.0f * cos_ph(m);

    float acc[5][4];
    #pragma unroll
    for (int j = 0; j < 5; j++)
        #pragma unroll
        for (int u = 0; u < 4; u++) acc[j][u] = 0.0f;

    for (int c = 0; c < 2; c++) {
        int kc = k0 + 64 * c;
        __syncthreads();
        // W tile fill (gk folded, hi/lo split)
        for (int idx = tid; idx < 32 * 84; idx += 256) {
            int kh = idx / 84, i = idx % 84;
            int k = kc + 2 * kh;
            float w0 = 0.0f, w1 = 0.0f;
            if (i < DIN) {
                float2 v = *reinterpret_cast<const float2*>(Wc + i * WSZ + k);
                w0 = v.x; w1 = v.y;
            } else if (i == DIN) {
                float2 v = *reinterpret_cast<const float2*>(bc + k);
                w0 = v.x; w1 = v.y;
            }
            w0 *= (k == 0) ? 1.0f : 2.0f;
            w1 *= (k + 1 == WSZ - 1) ? 1.0f : 2.0f;
            __half h0 = __float2half_rn(w0), h1 = __float2half_rn(w1);
            float l0 = w0 - __half2float(h0), l1 = w1 - __half2float(h1);
            sW[kh][i] = make_uint2(pack_hh(h0, h1), pack_h2(l0, l1));
        }
        // cosine tile: 8 pairs per thread via Chebyshev, hi/lo split
        {
            int ks0 = kc + 16 * q;
            int ph = (int)(((long long)ks0 * (long long)m) % IRL);
            float x0 = cos_ph(ph);
            int ph1 = ph + m; if (ph1 >= IRL) ph1 -= IRL;
            float x1 = cos_ph(ph1);
            #pragma unroll
            for (int s = 0; s < 8; s++) {
                __half h0 = __float2half_rn(x0), h1 = __float2half_rn(x1);
                float l0 = x0 - __half2float(h0), l1 = x1 - __half2float(h1);
                sC[8 * q + s][mi_l] = make_uint2(pack_hh(h0, h1), pack_h2(l0, l1));
                float x2 = fmaf(tc2, x1, -x0);
                float x3 = fmaf(tc2, x2, -x1);
                x0 = x2; x1 = x3;
            }
        }
        __syncthreads();
        #pragma unroll
        for (int ks = 0; ks < 4; ks++) {
            int khb = ks * 8;
            uint2 A0 = sC[khb + cq][tw + r];
            uint2 A1 = sC[khb + cq][tw + r + 8];
            uint2 A2 = sC[khb + cq + 4][tw + r];
            uint2 A3 = sC[khb + cq + 4][tw + r + 8];
            #pragma unroll
            for (int j = 0; j < 5; j++) {
                int nf = ng * 5 + j;
                uint2 B0 = sW[khb + cq][nf * 8 + r];
                uint2 B1 = sW[khb + cq + 4][nf * 8 + r];
                HMMA16(acc[j], A0.x, A1.x, A2.x, A3.x, B0.x, B1.x);  // ch*wh
                HMMA16(acc[j], A0.x, A1.x, A2.x, A3.x, B0.y, B1.y);  // ch*wl
                HMMA16(acc[j], A0.y, A1.y, A2.y, A3.y, B0.x, B1.x);  // cl*wh
            }
        }
    }

    // write with Hann scale
    int mia = mi0 + tw + r, mib = mia + 8;
    int ja = (mia >= 2) ? (mia - 2) : (1022 - mia);
    int jb = (mib >= 2) ? (mib - 2) : (1022 - mib);
    float sca = (0.5f - 0.5f * cospif((float)(ja + 2) * (1.0f / 512.0f))) * (1.0f / 16382.0f);
    float scb = (0.5f - 0.5f * cospif((float)(jb + 2) * (1.0f / 512.0f))) * (1.0f / 16382.0f);
    #pragma unroll
    for (int j = 0; j < 5; j++) {
        int i0 = (ng * 5 + j) * 8 + 2 * cq;
        if (i0 < NA) {
            atomicAdd(&g_D[mia * NA + i0], acc[j][0] * sca);
            atomicAdd(&g_D[mib * NA + i0], acc[j][2] * scb);
        }
        if (i0 + 1 < NA) {
            atomicAdd(&g_D[mia * NA + i0 + 1], acc[j][1] * sca);
            atomicAdd(&g_D[mib * NA + i0 + 1], acc[j][3] * scb);
        }
    }
}

// ---------------------------------------------------------------------------
// Tensor-core folded FIR, fp16 m16n8k16 (unchanged from R9 WIN).
#define FSTH 136
__global__ void __launch_bounds__(256) k_conv_tc2(const float* __restrict__ eps) {
    __shared__ float    sN[1152];
    __shared__ unsigned sF[16 * FSTH];
    __shared__ unsigned sCf[16 * 72];
    int tid = threadIdx.x;
    int lane = tid & 31, w = tid >> 5;
    int t0 = blockIdx.x * 128;
    int y  = blockIdx.y;
    int c0 = (y == 0) ? 0 : (5 + 4 * (y - 1));
    int c1 = c0 + ((y == 0) ? 5 : 4);

    float mean0 = g_mean[0];
    unsigned encm = g_max_u;
    float gmax = (encm & 0x80000000u) ? __uint_as_float(encm & 0x7fffffffu)
                                      : __uint_as_float(~encm);
    float inv = 1.0f / gmax;
    for (int s = tid; s < 1152; s += 256) {
        int u = t0 - 512 + s;
        sN[s] = (u >= 0 && u < WSZ) ? (mean0 + eps[u]) * inv : 0.0f;
    }

    int r = lane >> 2, cq = lane & 3;
    int tw = w * 16;
    float acc[9][4];
    #pragma unroll
    for (int nf = 0; nf < 9; nf++)
        #pragma unroll
        for (int q = 0; q < 4; q++) acc[nf][q] = 0.0f;

    for (int c = c0; c < c1; c++) {
        int dd0 = 32 * c;
        __syncthreads();
        for (int idx = tid; idx < 16 * 128; idx += 256) {
            int kh = idx >> 7, tt = idx & 127;
            int x = 512 + tt;
            float f[2];
            #pragma unroll
            for (int p = 0; p < 2; p++) {
                int dd = dd0 + 2 * kh + p;
                float v;
                if (dd < 510)       { int d = dd + 1; v = sN[x + d] + sN[x - d]; }
                else if (dd == 510) v = sN[x];
                else if (dd == 511) v = sN[x - 511];
                else if (dd == 512) v = sN[x - 512];
                else                v = 0.0f;
                f[p] = v;
            }
            sF[kh * FSTH + tt] = pack_h2(f[0], f[1]);
        }
        for (int idx = tid; idx < 16 * 72; idx += 256) {
            int kh = idx / 72, i = idx % 72;
            float d[2];
            #pragma unroll
            for (int p = 0; p < 2; p++) {
                int dd = dd0 + 2 * kh + p;
                int mi;
                if (dd < 510)       mi = 511 - dd;
                else if (dd == 510) mi = 512;
                else if (dd == 511) mi = 1;
                else if (dd == 512) mi = 0;
                else                mi = -1;
                d[p] = (mi >= 0 && i < NA) ? g_D[mi * NA + i] : 0.0f;
            }
            sCf[kh * 72 + i] = pack_h2(d[0], d[1]);
        }
        __syncthreads();
        #pragma unroll
        for (int ks = 0; ks < 2; ks++) {
            int kh = ks * 8;
            unsigned a0 = sF[(kh + cq) * FSTH + tw + r];
            unsigned a1 = sF[(kh + cq) * FSTH + tw + r + 8];
            unsigned a2 = sF[(kh + cq + 4) * FSTH + tw + r];
            unsigned a3 = sF[(kh + cq + 4) * FSTH + tw + r + 8];
            #pragma unroll
            for (int nf = 0; nf < 9; nf++) {
                unsigned b0 = sCf[(kh + cq) * 72 + nf * 8 + r];
                unsigned b1 = sCf[(kh + cq + 4) * 72 + nf * 8 + r];
                asm volatile(
                    "mma.sync.aligned.m16n8k16.row.col.f32.f16.f16.f32 "
                    "{%0,%1,%2,%3}, {%4,%5,%6,%7}, {%8,%9}, {%0,%1,%2,%3};"
                    : "+f"(acc[nf][0]), "+f"(acc[nf][1]),
                      "+f"(acc[nf][2]), "+f"(acc[nf][3])
                    : "r"(a0), "r"(a1), "r"(a2), "r"(a3),
                      "r"(b0), "r"(b1));
            }
        }
    }

    int t = t0 + tw + r;
    #pragma unroll
    for (int nf = 0; nf < 9; nf++) {
        int i0 = nf * 8 + 2 * cq;
        if (i0 < NA) {
            atomicAdd(&g_P[i0 * WSZ + t],     acc[nf][0]);
            atomicAdd(&g_P[i0 * WSZ + t + 8], acc[nf][2]);
        }
        if (i0 + 1 < NA) {
            atomicAdd(&g_P[(i0 + 1) * WSZ + t],     acc[nf][1]);
            atomicAdd(&g_P[(i0 + 1) * WSZ + t + 8], acc[nf][3]);
        }
    }
}

// ---------------------------------------------------------------------------
// k_out via fp16 m16n8k16 (unchanged from R9 WIN).
#define KO_TT 128
#define KO_KH 40
#define PSTH 136
#define XSTH 44
__global__ void __launch_bounds__(256) k_out_tc(const float* __restrict__ vel,
                                                const float* __restrict__ Kin,
                                                float* __restrict__ out) {
    __shared__ unsigned sP[KO_KH * PSTH];
    __shared__ unsigned sX[64 * XSTH];
    __shared__ float    sA[64];
    int tid = threadIdx.x, lane = tid & 31, w = tid >> 5;
    int t0 = blockIdx.x * KO_TT, b0 = blockIdx.y * 64;

    for (int idx = tid; idx < KO_KH * KO_TT; idx += 256) {
        int kh = idx >> 7, tt = idx & 127;
        int i0 = 2 * kh;
        float v0 = (i0     < NA) ? g_P[i0 * WSZ + t0 + tt]       : 0.0f;
        float v1 = (i0 + 1 < NA) ? g_P[(i0 + 1) * WSZ + t0 + tt] : 0.0f;
        sP[kh * PSTH + tt] = pack_h2(v0, v1);
    }
    for (int idx = tid; idx < 64 * KO_KH; idx += 256) {
        int bb = idx / KO_KH, kh = idx % KO_KH;
        int b = b0 + bb;
        float x[2];
        #pragma unroll
        for (int p = 0; p < 2; p++) {
            int i = 2 * kh + p;
            if (i < 64)       x[p] = vel[b * 64 + i];
            else if (i == 64) x[p] = Kin[b] * INV_MAXSTEPS;
            else if (i == 65) x[p] = 1.0f;
            else              x[p] = 0.0f;
        }
        sX[bb * XSTH + kh] = pack_h2(x[0], x[1]);
    }
    if (tid < 64) sA[tid] = g_amps[b0 + tid];
    __syncthreads();

    int wb = w & 1, wt = w >> 1;
    int r = lane >> 2, cq = lane & 3;
    float c[2][4][4];
    #pragma unroll
    for (int mf = 0; mf < 2; mf++)
        #pragma unroll
        for (int nf = 0; nf < 4; nf++)
            #pragma unroll
            for (int q = 0; q < 4; q++) c[mf][nf][q] = 0.0f;

    #pragma unroll
    for (int s = 0; s < KO_KH / 8; s++) {
        int kh = s * 8;
        unsigned a[2][4];
        #pragma unroll
        for (int mf = 0; mf < 2; mf++) {
            int rb = wb * 32 + mf * 16 + r;
            a[mf][0] = sX[rb * XSTH + kh + cq];
            a[mf][1] = sX[(rb + 8) * XSTH + kh + cq];
            a[mf][2] = sX[rb * XSTH + kh + cq + 4];
            a[mf][3] = sX[(rb + 8) * XSTH + kh + cq + 4];
        }
        unsigned bf[4][2];
        #pragma unroll
        for (int nf = 0; nf < 4; nf++) {
            int ct = wt * 32 + nf * 8 + r;
            bf[nf][0] = sP[(kh + cq) * PSTH + ct];
            bf[nf][1] = sP[(kh + cq + 4) * PSTH + ct];
        }
        #pragma unroll
        for (int mf = 0; mf < 2; mf++)
            #pragma unroll
            for (int nf = 0; nf < 4; nf++) {
                asm volatile(
                    "mma.sync.aligned.m16n8k16.row.col.f32.f16.f16.f32 "
                    "{%0,%1,%2,%3}, {%4,%5,%6,%7}, {%8,%9}, {%0,%1,%2,%3};"
                    : "+f"(c[mf][nf][0]), "+f"(c[mf][nf][1]),
                      "+f"(c[mf][nf][2]), "+f"(c[mf][nf][3])
                    : "r"(a[mf][0]), "r"(a[mf][1]), "r"(a[mf][2]), "r"(a[mf][3]),
                      "r"(bf[nf][0]), "r"(bf[nf][1]));
            }
    }

    #pragma unroll
    for (int mf = 0; mf < 2; mf++) {
        int rbl = wb * 32 + mf * 16 + r;
        float a1 = sA[rbl], a2 = sA[rbl + 8];
        int rb = b0 + rbl;
        #pragma unroll
        for (int nf = 0; nf < 4; nf++) {
            int ct = t0 + wt * 32 + nf * 8 + 2 * cq;
            float2 o1 = make_float2(a1 * c[mf][nf][0], a1 * c[mf][nf][1]);
            float2 o2 = make_float2(a2 * c[mf][nf][2], a2 * c[mf][nf][3]);
            *reinterpret_cast<float2*>(&out[rb * WSZ + ct])       = o1;
            *reinterpret_cast<float2*>(&out[(rb + 8) * WSZ + ct]) = o2;
        }
    }
}

// ---------------------------------------------------------------------------
static cudaStream_t s_aux1, s_aux2;
static cudaEvent_t  ev_root, ev_j1, ev_j2;
namespace {
struct StreamBoot {
    StreamBoot() {
        cudaStreamCreateWithFlags(&s_aux1, cudaStreamNonBlocking);
        cudaStreamCreateWithFlags(&s_aux2, cudaStreamNonBlocking);
        cudaEventCreateWithFlags(&ev_root, cudaEventDisableTiming);
        cudaEventCreateWithFlags(&ev_j1,   cudaEventDisableTiming);
        cudaEventCreateWithFlags(&ev_j2,   cudaEventDisableTiming);
    }
};
static StreamBoot g_stream_boot;
}

extern "C" void kernel_launch(void* const* d_in, const int* in_sizes, int n_in,
                              void* d_out, int out_size) {
    const float* vel = (const float*)d_in[0];
    const float* Kin = (const float*)d_in[1];
    const float* eps = (const float*)d_in[2];
    const float* Wc  = (const float*)d_in[3];
    const float* bc  = (const float*)d_in[4];
    const float* Wa  = (const float*)d_in[5];
    const float* ba  = (const float*)d_in[6];
    const float* Wm  = (const float*)d_in[7];
    const float* bm  = (const float*)d_in[8];
    float* out = (float*)d_out;

    k_init  <<< (NA * WSZ / 4 + 255) / 256, 256 >>> ();
    cudaEventRecord(ev_root, 0);
    cudaStreamWaitEvent(s_aux1, ev_root, 0);
    cudaStreamWaitEvent(s_aux2, ev_root, 0);

    k_stats <<< 32, 1024, 0, s_aux1 >>> (vel, Kin, Wa, ba, Wm, bm, out, out_size);
    k_gmax  <<< 1024, 256, 0, s_aux1 >>> (eps);
    cudaEventRecord(ev_j1, s_aux1);

    k_mmat_tc <<< dim3(8, MMT_KSPLIT), 256 >>> (Wc, bc);

    k_center<<< dim3(NA, 8), 256, 0, s_aux2 >>> (Wc, bc);
    cudaEventRecord(ev_j2, s_aux2);

    cudaStreamWaitEvent(0, ev_j1, 0);
    cudaStreamWaitEvent(0, ev_j2, 0);
    k_conv_tc2<<< dim3(64, 4), 256 >>> (eps);
    k_out_tc<<< dim3(WSZ / KO_TT, BATCH / 64), 256 >>> (vel, Kin, out);
}

// round 11
// speedup vs baseline: 2.5588x; 1.1396x over previous
#include <cuda_runtime.h>
#include <cuda_fp16.h>
#include <math.h>

#define BATCH 1024
#define WSZ   8192
#define DIN   65
#define NA    66
#define IRL   16382
#define MI_N  513
#define INV_MAXSTEPS (1.0f/2799.0f)
#define PI_OVER_8191 (3.14159265358979323846f/8191.0f)

__device__ float        g_mean[BATCH];
__device__ float        g_amps[BATCH];
__device__ unsigned int g_max_u;
__device__ float        g_D[MI_N * NA];   // windowed DCT columns [mi][i], h folded
__device__ float        g_P[NA * WSZ];    // conv result [i][t]
// Pre-split W (gk folded): [kh][i] packs (k=2kh, 2kh+1) as half2; stride 86.
__device__ unsigned     g_Wh2[4096 * 86];
__device__ unsigned     g_Wl2[4096 * 86];

__device__ __forceinline__ float cos_ph(int p) {   // p in [0, IRL)
    int p2 = (p >= 8191) ? (p - IRL) : p;
    return __cosf((float)p2 * PI_OVER_8191);
}
__device__ __forceinline__ unsigned pack_h2(float a, float b) {
    __half2 h = __floats2half2_rn(a, b);
    return *reinterpret_cast<unsigned*>(&h);
}
__device__ __forceinline__ unsigned pack_hh(__half a, __half b) {
    __half2 h = __halves2half2(a, b);
    return *reinterpret_cast<unsigned*>(&h);
}

#define HMMA16(C, A0, A1, A2, A3, B0, B1)                                   \
    asm volatile(                                                           \
        "mma.sync.aligned.m16n8k16.row.col.f32.f16.f16.f32 "                \
        "{%0,%1,%2,%3}, {%4,%5,%6,%7}, {%8,%9}, {%0,%1,%2,%3};"             \
        : "+f"((C)[0]), "+f"((C)[1]), "+f"((C)[2]), "+f"((C)[3])            \
        : "r"(A0), "r"(A1), "r"(A2), "r"(A3), "r"(B0), "r"(B1))

// ---------------------------------------------------------------------------
__global__ void k_init() {
    int idx = blockIdx.x * blockDim.x + threadIdx.x;
    if (idx < (NA * WSZ) / 4)
        reinterpret_cast<float4*>(g_P)[idx] = make_float4(0.f, 0.f, 0.f, 0.f);
    if (idx < MI_N * NA) g_D[idx] = 0.0f;
    if (idx == 0)        g_max_u = 0u;
}

// ---------------------------------------------------------------------------
// One-time W split: w = gk*W[i][k]; hi = rn-fp16, lo = w - hi.
__global__ void k_wprep(const float* __restrict__ Wc, const float* __restrict__ bc) {
    int idx = blockIdx.x * 256 + threadIdx.x;
    if (idx >= 4096 * 86) return;
    int kh = idx / 86, i = idx % 86;
    int k = 2 * kh;
    float w0 = 0.0f, w1 = 0.0f;
    if (i < DIN) {
        float2 v = *reinterpret_cast<const float2*>(Wc + i * WSZ + k);
        w0 = v.x; w1 = v.y;
    } else if (i == DIN) {
        float2 v = *reinterpret_cast<const float2*>(bc + k);
        w0 = v.x; w1 = v.y;
    }
    w0 *= (k == 0) ? 1.0f : 2.0f;
    w1 *= (k + 1 == WSZ - 1) ? 1.0f : 2.0f;
    __half h0 = __float2half_rn(w0), h1 = __float2half_rn(w1);
    float l0 = w0 - __half2float(h0), l1 = w1 - __half2float(h1);
    g_Wh2[idx] = pack_hh(h0, h1);
    g_Wl2[idx] = pack_h2(l0, l1);
}

// ---------------------------------------------------------------------------
// Center column mi=512 (m=8191): cos = (-1)^k, h=1. Split-k x8 + atomicAdd.
__global__ void k_center(const float* __restrict__ Wc, const float* __restrict__ bc) {
    __shared__ float red[8];
    int i = blockIdx.x;
    int kc = blockIdx.y * 1024;
    const float* row = (i < DIN) ? &Wc[i * WSZ] : bc;
    float s = 0.0f;
    for (int k = kc + threadIdx.x; k < kc + 1024; k += 256) {
        float gk = (k == 0 || k == WSZ - 1) ? 1.0f : 2.0f;
        float sgn = (k & 1) ? -1.0f : 1.0f;
        s += row[k] * gk * sgn;
    }
    #pragma unroll
    for (int o = 16; o; o >>= 1) s += __shfl_xor_sync(0xffffffffu, s, o);
    if ((threadIdx.x & 31) == 0) red[threadIdx.x >> 5] = s;
    __syncthreads();
    if (threadIdx.x == 0) {
        float t = 0.0f;
        #pragma unroll
        for (int w = 0; w < 8; w++) t += red[w];
        atomicAdd(&g_D[512 * NA + i], t * (1.0f / 16382.0f));
    }
}

// ---------------------------------------------------------------------------
__global__ void k_stats(const float* __restrict__ vel, const float* __restrict__ Kin,
                        const float* __restrict__ Wa, const float* __restrict__ ba,
                        const float* __restrict__ Wm, const float* __restrict__ bm,
                        float* __restrict__ out, int out_size) {
    int gw = (blockIdx.x * blockDim.x + threadIdx.x) >> 5;
    int lane = threadIdx.x & 31;
    if (gw >= BATCH) return;
    float sa = 0.0f, sm = 0.0f;
    #pragma unroll
    for (int i = lane; i < 64; i += 32) {
        float x = vel[gw * 64 + i];
        sa += x * Wa[i];
        sm += x * Wm[i];
    }
    if (lane == 0) {
        float xk = Kin[gw] * INV_MAXSTEPS;
        sa += xk * Wa[64];
        sm += xk * Wm[64];
    }
    #pragma unroll
    for (int o = 16; o; o >>= 1) {
        sa += __shfl_down_sync(0xffffffffu, sa, o);
        sm += __shfl_down_sync(0xffffffffu, sm, o);
    }
    if (lane == 0) {
        float m = tanhf(sm + bm[0]);
        float a = 1.0f / (1.0f + expf(-(sa + ba[0])));
        g_mean[gw] = m;
        g_amps[gw] = a;
        if (out_size >= BATCH * WSZ + BATCH)
            out[BATCH * WSZ + gw] = m;
    }
}

// ---------------------------------------------------------------------------
__global__ void k_gmax(const float* __restrict__ eps) {
    const int N4 = (BATCH * WSZ) / 4;
    const float NEG = __int_as_float(0xff800000);
    int stride = gridDim.x * blockDim.x;
    int i0 = blockIdx.x * blockDim.x + threadIdx.x;
    const float4* e4 = reinterpret_cast<const float4*>(eps);
    float a0 = NEG, a1 = NEG, a2 = NEG, a3 = NEG;
    for (int j = i0; j < N4; j += 4 * stride) {
        int j1 = j + stride, j2 = j + 2 * stride, j3 = j + 3 * stride;
        float4 v0 = e4[j];
        float4 v1 = (j1 < N4) ? e4[j1] : make_float4(NEG,NEG,NEG,NEG);
        float4 v2 = (j2 < N4) ? e4[j2] : make_float4(NEG,NEG,NEG,NEG);
        float4 v3 = (j3 < N4) ? e4[j3] : make_float4(NEG,NEG,NEG,NEG);
        float m0 = g_mean[j >> 11];
        float m1 = (j1 < N4) ? g_mean[j1 >> 11] : 0.0f;
        float m2 = (j2 < N4) ? g_mean[j2 >> 11] : 0.0f;
        float m3 = (j3 < N4) ? g_mean[j3 >> 11] : 0.0f;
        a0 = fmaxf(a0, m0 + fmaxf(fmaxf(v0.x, v0.y), fmaxf(v0.z, v0.w)));
        a1 = fmaxf(a1, m1 + fmaxf(fmaxf(v1.x, v1.y), fmaxf(v1.z, v1.w)));
        a2 = fmaxf(a2, m2 + fmaxf(fmaxf(v2.x, v2.y), fmaxf(v2.z, v2.w)));
        a3 = fmaxf(a3, m3 + fmaxf(fmaxf(v3.x, v3.y), fmaxf(v3.z, v3.w)));
    }
    float lm = fmaxf(fmaxf(a0, a1), fmaxf(a2, a3));
    #pragma unroll
    for (int o = 16; o; o >>= 1)
        lm = fmaxf(lm, __shfl_xor_sync(0xffffffffu, lm, o));
    if ((threadIdx.x & 31) == 0) {
        unsigned b = __float_as_uint(lm);
        unsigned enc = (b & 0x80000000u) ? ~b : (b | 0x80000000u);
        atomicMax(&g_max_u, enc);
    }
}

// ---------------------------------------------------------------------------
// Tensor-core DCT: D[mi][i] = h/16382 * sum_k gk*W[i][k]*cos(2pi*k*m/IRL),
// m = 7679+mi. cos in rn-fp16 (hi only); W pre-split hi/lo from g_W*2.
// Tile 64 mi x 80 i; grid (8 mi-tiles, 64 k-splits of 128). 256 thr.
#define MMT_KSPLIT 64
__global__ void __launch_bounds__(256) k_mmat_tc(const float* __restrict__ Wc,
                                                 const float* __restrict__ bc) {
    __shared__ __align__(16) unsigned sC[32 * 68];   // [kh][mi] cos pairs
    __shared__ __align__(16) unsigned sWh[32 * 86];  // [kh][i] hi pairs
    __shared__ __align__(16) unsigned sWl[32 * 86];  // [kh][i] lo pairs
    int tid = threadIdx.x, lane = tid & 31, w = tid >> 5;
    int mi0 = blockIdx.x * 64;
    int k0  = blockIdx.y * 128;
    int r = lane >> 2, cq = lane & 3;
    int mf = w & 3, ng = w >> 2;
    int tw = mf * 16;

    int mi_l = tid & 63, q = tid >> 6;
    int m = 7679 + mi0 + mi_l;
    float tc2 = 2.0f * cos_ph(m);

    float acc[5][4];
    #pragma unroll
    for (int j = 0; j < 5; j++)
        #pragma unroll
        for (int u = 0; u < 4; u++) acc[j][u] = 0.0f;

    for (int c = 0; c < 2; c++) {
        int kc = k0 + 64 * c;
        int kcH = kc >> 1;
        __syncthreads();
        // W tiles: pure linear uint4 copy (pre-split in k_wprep)
        {
            const uint4* gh = reinterpret_cast<const uint4*>(g_Wh2 + kcH * 86);
            const uint4* gl = reinterpret_cast<const uint4*>(g_Wl2 + kcH * 86);
            uint4* shh = reinterpret_cast<uint4*>(sWh);
            uint4* sll = reinterpret_cast<uint4*>(sWl);
            for (int idx = tid; idx < (32 * 86) / 4; idx += 256) {
                shh[idx] = gh[idx];
                sll[idx] = gl[idx];
            }
        }
        // cosine tile: 8 pairs per thread via Chebyshev, rn-fp16 pack
        {
            int ks0 = kc + 16 * q;
            int ph = (int)(((long long)ks0 * (long long)m) % IRL);
            float x0 = cos_ph(ph);
            int ph1 = ph + m; if (ph1 >= IRL) ph1 -= IRL;
            float x1 = cos_ph(ph1);
            #pragma unroll
            for (int s = 0; s < 8; s++) {
                sC[(8 * q + s) * 68 + mi_l] = pack_h2(x0, x1);
                float x2 = fmaf(tc2, x1, -x0);
                float x3 = fmaf(tc2, x2, -x1);
                x0 = x2; x1 = x3;
            }
        }
        __syncthreads();
        #pragma unroll
        for (int ks = 0; ks < 4; ks++) {
            int khb = ks * 8;
            unsigned A0 = sC[(khb + cq) * 68 + tw + r];
            unsigned A1 = sC[(khb + cq) * 68 + tw + r + 8];
            unsigned A2 = sC[(khb + cq + 4) * 68 + tw + r];
            unsigned A3 = sC[(khb + cq + 4) * 68 + tw + r + 8];
            #pragma unroll
            for (int j = 0; j < 5; j++) {
                int col = (ng * 5 + j) * 8 + r;
                unsigned B0h = sWh[(khb + cq) * 86 + col];
                unsigned B1h = sWh[(khb + cq + 4) * 86 + col];
                unsigned B0l = sWl[(khb + cq) * 86 + col];
                unsigned B1l = sWl[(khb + cq + 4) * 86 + col];
                HMMA16(acc[j], A0, A1, A2, A3, B0h, B1h);   // c*wh
                HMMA16(acc[j], A0, A1, A2, A3, B0l, B1l);   // c*wl
            }
        }
    }

    int mia = mi0 + tw + r, mib = mia + 8;
    int ja = (mia >= 2) ? (mia - 2) : (1022 - mia);
    int jb = (mib >= 2) ? (mib - 2) : (1022 - mib);
    float sca = (0.5f - 0.5f * cospif((float)(ja + 2) * (1.0f / 512.0f))) * (1.0f / 16382.0f);
    float scb = (0.5f - 0.5f * cospif((float)(jb + 2) * (1.0f / 512.0f))) * (1.0f / 16382.0f);
    #pragma unroll
    for (int j = 0; j < 5; j++) {
        int i0 = (ng * 5 + j) * 8 + 2 * cq;
        if (i0 < NA) {
            atomicAdd(&g_D[mia * NA + i0], acc[j][0] * sca);
            atomicAdd(&g_D[mib * NA + i0], acc[j][2] * scb);
        }
        if (i0 + 1 < NA) {
            atomicAdd(&g_D[mia * NA + i0 + 1], acc[j][1] * sca);
            atomicAdd(&g_D[mib * NA + i0 + 1], acc[j][3] * scb);
        }
    }
}

// ---------------------------------------------------------------------------
// Tensor-core folded FIR, fp16 m16n8k16 (unchanged from R9 WIN).
#define FSTH 136
__global__ void __launch_bounds__(256) k_conv_tc2(const float* __restrict__ eps) {
    __shared__ float    sN[1152];
    __shared__ unsigned sF[16 * FSTH];
    __shared__ unsigned sCf[16 * 72];
    int tid = threadIdx.x;
    int lane = tid & 31, w = tid >> 5;
    int t0 = blockIdx.x * 128;
    int y  = blockIdx.y;
    int c0 = (y == 0) ? 0 : (5 + 4 * (y - 1));
    int c1 = c0 + ((y == 0) ? 5 : 4);

    float mean0 = g_mean[0];
    unsigned encm = g_max_u;
    float gmax = (encm & 0x80000000u) ? __uint_as_float(encm & 0x7fffffffu)
                                      : __uint_as_float(~encm);
    float inv = 1.0f / gmax;
    for (int s = tid; s < 1152; s += 256) {
        int u = t0 - 512 + s;
        sN[s] = (u >= 0 && u < WSZ) ? (mean0 + eps[u]) * inv : 0.0f;
    }

    int r = lane >> 2, cq = lane & 3;
    int tw = w * 16;
    float acc[9][4];
    #pragma unroll
    for (int nf = 0; nf < 9; nf++)
        #pragma unroll
        for (int q = 0; q < 4; q++) acc[nf][q] = 0.0f;

    for (int c = c0; c < c1; c++) {
        int dd0 = 32 * c;
        __syncthreads();
        for (int idx = tid; idx < 16 * 128; idx += 256) {
            int kh = idx >> 7, tt = idx & 127;
            int x = 512 + tt;
            float f[2];
            #pragma unroll
            for (int p = 0; p < 2; p++) {
                int dd = dd0 + 2 * kh + p;
                float v;
                if (dd < 510)       { int d = dd + 1; v = sN[x + d] + sN[x - d]; }
                else if (dd == 510) v = sN[x];
                else if (dd == 511) v = sN[x - 511];
                else if (dd == 512) v = sN[x - 512];
                else                v = 0.0f;
                f[p] = v;
            }
            sF[kh * FSTH + tt] = pack_h2(f[0], f[1]);
        }
        for (int idx = tid; idx < 16 * 72; idx += 256) {
            int kh = idx / 72, i = idx % 72;
            float d[2];
            #pragma unroll
            for (int p = 0; p < 2; p++) {
                int dd = dd0 + 2 * kh + p;
                int mi;
                if (dd < 510)       mi = 511 - dd;
                else if (dd == 510) mi = 512;
                else if (dd == 511) mi = 1;
                else if (dd == 512) mi = 0;
                else                mi = -1;
                d[p] = (mi >= 0 && i < NA) ? g_D[mi * NA + i] : 0.0f;
            }
            sCf[kh * 72 + i] = pack_h2(d[0], d[1]);
        }
        __syncthreads();
        #pragma unroll
        for (int ks = 0; ks < 2; ks++) {
            int kh = ks * 8;
            unsigned a0 = sF[(kh + cq) * FSTH + tw + r];
            unsigned a1 = sF[(kh + cq) * FSTH + tw + r + 8];
            unsigned a2 = sF[(kh + cq + 4) * FSTH + tw + r];
            unsigned a3 = sF[(kh + cq + 4) * FSTH + tw + r + 8];
            #pragma unroll
            for (int nf = 0; nf < 9; nf++) {
                unsigned b0 = sCf[(kh + cq) * 72 + nf * 8 + r];
                unsigned b1 = sCf[(kh + cq + 4) * 72 + nf * 8 + r];
                HMMA16(acc[nf], a0, a1, a2, a3, b0, b1);
            }
        }
    }

    int t = t0 + tw + r;
    #pragma unroll
    for (int nf = 0; nf < 9; nf++) {
        int i0 = nf * 8 + 2 * cq;
        if (i0 < NA) {
            atomicAdd(&g_P[i0 * WSZ + t],     acc[nf][0]);
            atomicAdd(&g_P[i0 * WSZ + t + 8], acc[nf][2]);
        }
        if (i0 + 1 < NA) {
            atomicAdd(&g_P[(i0 + 1) * WSZ + t],     acc[nf][1]);
            atomicAdd(&g_P[(i0 + 1) * WSZ + t + 8], acc[nf][3]);
        }
    }
}

// ---------------------------------------------------------------------------
// k_out via fp16 m16n8k16 (unchanged from R9 WIN).
#define KO_TT 128
#define KO_KH 40
#define PSTH 136
#define XSTH 44
__global__ void __launch_bounds__(256) k_out_tc(const float* __restrict__ vel,
                                                const float* __restrict__ Kin,
                                                float* __restrict__ out) {
    __shared__ unsigned sP[KO_KH * PSTH];
    __shared__ unsigned sX[64 * XSTH];
    __shared__ float    sA[64];
    int tid = threadIdx.x, lane = tid & 31, w = tid >> 5;
    int t0 = blockIdx.x * KO_TT, b0 = blockIdx.y * 64;

    for (int idx = tid; idx < KO_KH * KO_TT; idx += 256) {
        int kh = idx >> 7, tt = idx & 127;
        int i0 = 2 * kh;
        float v0 = (i0     < NA) ? g_P[i0 * WSZ + t0 + tt]       : 0.0f;
        float v1 = (i0 + 1 < NA) ? g_P[(i0 + 1) * WSZ + t0 + tt] : 0.0f;
        sP[kh * PSTH + tt] = pack_h2(v0, v1);
    }
    for (int idx = tid; idx < 64 * KO_KH; idx += 256) {
        int bb = idx / KO_KH, kh = idx % KO_KH;
        int b = b0 + bb;
        float x[2];
        #pragma unroll
        for (int p = 0; p < 2; p++) {
            int i = 2 * kh + p;
            if (i < 64)       x[p] = vel[b * 64 + i];
            else if (i == 64) x[p] = Kin[b] * INV_MAXSTEPS;
            else if (i == 65) x[p] = 1.0f;
            else              x[p] = 0.0f;
        }
        sX[bb * XSTH + kh] = pack_h2(x[0], x[1]);
    }
    if (tid < 64) sA[tid] = g_amps[b0 + tid];
    __syncthreads();

    int wb = w & 1, wt = w >> 1;
    int r = lane >> 2, cq = lane & 3;
    float c[2][4][4];
    #pragma unroll
    for (int mf = 0; mf < 2; mf++)
        #pragma unroll
        for (int nf = 0; nf < 4; nf++)
            #pragma unroll
            for (int q = 0; q < 4; q++) c[mf][nf][q] = 0.0f;

    #pragma unroll
    for (int s = 0; s < KO_KH / 8; s++) {
        int kh = s * 8;
        unsigned a[2][4];
        #pragma unroll
        for (int mf = 0; mf < 2; mf++) {
            int rb = wb * 32 + mf * 16 + r;
            a[mf][0] = sX[rb * XSTH + kh + cq];
            a[mf][1] = sX[(rb + 8) * XSTH + kh + cq];
            a[mf][2] = sX[rb * XSTH + kh + cq + 4];
            a[mf][3] = sX[(rb + 8) * XSTH + kh + cq + 4];
        }
        unsigned bf[4][2];
        #pragma unroll
        for (int nf = 0; nf < 4; nf++) {
            int ct = wt * 32 + nf * 8 + r;
            bf[nf][0] = sP[(kh + cq) * PSTH + ct];
            bf[nf][1] = sP[(kh + cq + 4) * PSTH + ct];
        }
        #pragma unroll
        for (int mf = 0; mf < 2; mf++)
            #pragma unroll
            for (int nf = 0; nf < 4; nf++)
                HMMA16(c[mf][nf], a[mf][0], a[mf][1], a[mf][2], a[mf][3],
                       bf[nf][0], bf[nf][1]);
    }

    #pragma unroll
    for (int mf = 0; mf < 2; mf++) {
        int rbl = wb * 32 + mf * 16 + r;
        float a1 = sA[rbl], a2 = sA[rbl + 8];
        int rb = b0 + rbl;
        #pragma unroll
        for (int nf = 0; nf < 4; nf++) {
            int ct = t0 + wt * 32 + nf * 8 + 2 * cq;
            float2 o1 = make_float2(a1 * c[mf][nf][0], a1 * c[mf][nf][1]);
            float2 o2 = make_float2(a2 * c[mf][nf][2], a2 * c[mf][nf][3]);
            *reinterpret_cast<float2*>(&out[rb * WSZ + ct])       = o1;
            *reinterpret_cast<float2*>(&out[(rb + 8) * WSZ + ct]) = o2;
        }
    }
}

// ---------------------------------------------------------------------------
static cudaStream_t s_aux1, s_aux2;
static cudaEvent_t  ev_root, ev_j1, ev_j2;
namespace {
struct StreamBoot {
    StreamBoot() {
        cudaStreamCreateWithFlags(&s_aux1, cudaStreamNonBlocking);
        cudaStreamCreateWithFlags(&s_aux2, cudaStreamNonBlocking);
        cudaEventCreateWithFlags(&ev_root, cudaEventDisableTiming);
        cudaEventCreateWithFlags(&ev_j1,   cudaEventDisableTiming);
        cudaEventCreateWithFlags(&ev_j2,   cudaEventDisableTiming);
    }
};
static StreamBoot g_stream_boot;
}

extern "C" void kernel_launch(void* const* d_in, const int* in_sizes, int n_in,
                              void* d_out, int out_size) {
    const float* vel = (const float*)d_in[0];
    const float* Kin = (const float*)d_in[1];
    const float* eps = (const float*)d_in[2];
    const float* Wc  = (const float*)d_in[3];
    const float* bc  = (const float*)d_in[4];
    const float* Wa  = (const float*)d_in[5];
    const float* ba  = (const float*)d_in[6];
    const float* Wm  = (const float*)d_in[7];
    const float* bm  = (const float*)d_in[8];
    float* out = (float*)d_out;

    k_init  <<< (NA * WSZ / 4 + 255) / 256, 256 >>> ();
    k_wprep <<< (4096 * 86 + 255) / 256, 256 >>> (Wc, bc);
    cudaEventRecord(ev_root, 0);
    cudaStreamWaitEvent(s_aux1, ev_root, 0);
    cudaStreamWaitEvent(s_aux2, ev_root, 0);

    k_stats <<< 32, 1024, 0, s_aux1 >>> (vel, Kin, Wa, ba, Wm, bm, out, out_size);
    k_gmax  <<< 1024, 256, 0, s_aux1 >>> (eps);
    cudaEventRecord(ev_j1, s_aux1);

    k_mmat_tc <<< dim3(8, MMT_KSPLIT), 256 >>> (Wc, bc);

    k_center<<< dim3(NA, 8), 256, 0, s_aux2 >>> (Wc, bc);
    cudaEventRecord(ev_j2, s_aux2);

    cudaStreamWaitEvent(0, ev_j1, 0);
    cudaStreamWaitEvent(0, ev_j2, 0);
    k_conv_tc2<<< dim3(64, 4), 256 >>> (eps);
    k_out_tc<<< dim3(WSZ / KO_TT, BATCH / 64), 256 >>> (vel, Kin, out);
}

// round 12
// speedup vs baseline: 2.5684x; 1.0038x over previous
#include <cuda_runtime.h>
#include <cuda_fp16.h>
#include <math.h>

#define BATCH 1024
#define WSZ   8192
#define DIN   65
#define NA    66
#define IRL   16382
#define MI_N  513
#define INV_MAXSTEPS (1.0f/2799.0f)
#define PI_OVER_8191 (3.14159265358979323846f/8191.0f)

__device__ float        g_mean[BATCH];
__device__ float        g_amps[BATCH];
__device__ float        g_rowmax[BATCH];
__device__ unsigned int g_max_u;
__device__ float        g_D[MI_N * NA];   // windowed DCT columns [mi][i], h folded
__device__ float        g_P[NA * WSZ];    // conv result [i][t]
// Pre-split W (gk folded): [kh][i] packs (k=2kh, 2kh+1) as half2; stride 86.
__device__ unsigned     g_Wh2[4096 * 86];
__device__ unsigned     g_Wl2[4096 * 86];

__device__ __forceinline__ float cos_ph(int p) {   // p in [0, IRL)
    int p2 = (p >= 8191) ? (p - IRL) : p;
    return __cosf((float)p2 * PI_OVER_8191);
}
__device__ __forceinline__ unsigned pack_h2(float a, float b) {
    __half2 h = __floats2half2_rn(a, b);
    return *reinterpret_cast<unsigned*>(&h);
}
__device__ __forceinline__ unsigned pack_hh(__half a, __half b) {
    __half2 h = __halves2half2(a, b);
    return *reinterpret_cast<unsigned*>(&h);
}

#define HMMA16(C, A0, A1, A2, A3, B0, B1)                                   \
    asm volatile(                                                           \
        "mma.sync.aligned.m16n8k16.row.col.f32.f16.f16.f32 "                \
        "{%0,%1,%2,%3}, {%4,%5,%6,%7}, {%8,%9}, {%0,%1,%2,%3};"             \
        : "+f"((C)[0]), "+f"((C)[1]), "+f"((C)[2]), "+f"((C)[3])            \
        : "r"(A0), "r"(A1), "r"(A2), "r"(A3), "r"(B0), "r"(B1))

// ---------------------------------------------------------------------------
__global__ void k_initD() {
    int idx = blockIdx.x * blockDim.x + threadIdx.x;
    if (idx < MI_N * NA) g_D[idx] = 0.0f;
    if (idx == 0)        g_max_u = 0u;
}
__global__ void k_initP() {
    int idx = blockIdx.x * blockDim.x + threadIdx.x;
    if (idx < (NA * WSZ) / 4)
        reinterpret_cast<float4*>(g_P)[idx] = make_float4(0.f, 0.f, 0.f, 0.f);
}

// ---------------------------------------------------------------------------
// One-time W split: w = gk*W[i][k]; hi = rn-fp16, lo = w - hi.
__global__ void k_wprep(const float* __restrict__ Wc, const float* __restrict__ bc) {
    int idx = blockIdx.x * 256 + threadIdx.x;
    if (idx >= 4096 * 86) return;
    int kh = idx / 86, i = idx % 86;
    int k = 2 * kh;
    float w0 = 0.0f, w1 = 0.0f;
    if (i < DIN) {
        float2 v = *reinterpret_cast<const float2*>(Wc + i * WSZ + k);
        w0 = v.x; w1 = v.y;
    } else if (i == DIN) {
        float2 v = *reinterpret_cast<const float2*>(bc + k);
        w0 = v.x; w1 = v.y;
    }
    w0 *= (k == 0) ? 1.0f : 2.0f;
    w1 *= (k + 1 == WSZ - 1) ? 1.0f : 2.0f;
    __half h0 = __float2half_rn(w0), h1 = __float2half_rn(w1);
    float l0 = w0 - __half2float(h0), l1 = w1 - __half2float(h1);
    g_Wh2[idx] = pack_hh(h0, h1);
    g_Wl2[idx] = pack_h2(l0, l1);
}

// ---------------------------------------------------------------------------
// Center column mi=512 (m=8191): cos = (-1)^k, h=1. Split-k x8 + atomicAdd.
__global__ void k_center(const float* __restrict__ Wc, const float* __restrict__ bc) {
    __shared__ float red[8];
    int i = blockIdx.x;
    int kc = blockIdx.y * 1024;
    const float* row = (i < DIN) ? &Wc[i * WSZ] : bc;
    float s = 0.0f;
    for (int k = kc + threadIdx.x; k < kc + 1024; k += 256) {
        float gk = (k == 0 || k == WSZ - 1) ? 1.0f : 2.0f;
        float sgn = (k & 1) ? -1.0f : 1.0f;
        s += row[k] * gk * sgn;
    }
    #pragma unroll
    for (int o = 16; o; o >>= 1) s += __shfl_xor_sync(0xffffffffu, s, o);
    if ((threadIdx.x & 31) == 0) red[threadIdx.x >> 5] = s;
    __syncthreads();
    if (threadIdx.x == 0) {
        float t = 0.0f;
        #pragma unroll
        for (int w = 0; w < 8; w++) t += red[w];
        atomicAdd(&g_D[512 * NA + i], t * (1.0f / 16382.0f));
    }
}

// ---------------------------------------------------------------------------
__global__ void k_stats(const float* __restrict__ vel, const float* __restrict__ Kin,
                        const float* __restrict__ Wa, const float* __restrict__ ba,
                        const float* __restrict__ Wm, const float* __restrict__ bm,
                        float* __restrict__ out, int out_size) {
    int gw = (blockIdx.x * blockDim.x + threadIdx.x) >> 5;
    int lane = threadIdx.x & 31;
    if (gw >= BATCH) return;
    float sa = 0.0f, sm = 0.0f;
    #pragma unroll
    for (int i = lane; i < 64; i += 32) {
        float x = vel[gw * 64 + i];
        sa += x * Wa[i];
        sm += x * Wm[i];
    }
    if (lane == 0) {
        float xk = Kin[gw] * INV_MAXSTEPS;
        sa += xk * Wa[64];
        sm += xk * Wm[64];
    }
    #pragma unroll
    for (int o = 16; o; o >>= 1) {
        sa += __shfl_down_sync(0xffffffffu, sa, o);
        sm += __shfl_down_sync(0xffffffffu, sm, o);
    }
    if (lane == 0) {
        float m = tanhf(sm + bm[0]);
        float a = 1.0f / (1.0f + expf(-(sa + ba[0])));
        g_mean[gw] = m;
        g_amps[gw] = a;
        if (out_size >= BATCH * WSZ + BATCH)
            out[BATCH * WSZ + gw] = m;
    }
}

// ---------------------------------------------------------------------------
// Per-row max of eps: one block per row, 256 thr x 8 float4 (MLP=8, exact).
__global__ void __launch_bounds__(256) k_rowmax(const float* __restrict__ eps) {
    __shared__ float red[8];
    int b = blockIdx.x;
    const float4* row = reinterpret_cast<const float4*>(eps + b * WSZ);
    float4 v[8];
    #pragma unroll
    for (int s = 0; s < 8; s++) v[s] = row[threadIdx.x + 256 * s];
    float lm = __int_as_float(0xff800000);
    #pragma unroll
    for (int s = 0; s < 8; s++)
        lm = fmaxf(lm, fmaxf(fmaxf(v[s].x, v[s].y), fmaxf(v[s].z, v[s].w)));
    #pragma unroll
    for (int o = 16; o; o >>= 1)
        lm = fmaxf(lm, __shfl_xor_sync(0xffffffffu, lm, o));
    if ((threadIdx.x & 31) == 0) red[threadIdx.x >> 5] = lm;
    __syncthreads();
    if (threadIdx.x == 0) {
        float t = red[0];
        #pragma unroll
        for (int w = 1; w < 8; w++) t = fmaxf(t, red[w]);
        g_rowmax[b] = t;
    }
}

// Combine: gmax = max_b(mean[b] + rowmax[b]). 1 block, 1024 threads.
__global__ void k_combine() {
    int b = threadIdx.x;
    float lm = g_mean[b] + g_rowmax[b];
    #pragma unroll
    for (int o = 16; o; o >>= 1)
        lm = fmaxf(lm, __shfl_xor_sync(0xffffffffu, lm, o));
    if ((b & 31) == 0) {
        unsigned u = __float_as_uint(lm);
        unsigned enc = (u & 0x80000000u) ? ~u : (u | 0x80000000u);
        atomicMax(&g_max_u, enc);
    }
}

// ---------------------------------------------------------------------------
// Tensor-core DCT (unchanged from R11 WIN).
#define MMT_KSPLIT 64
__global__ void __launch_bounds__(256) k_mmat_tc(const float* __restrict__ Wc,
                                                 const float* __restrict__ bc) {
    __shared__ __align__(16) unsigned sC[32 * 68];
    __shared__ __align__(16) unsigned sWh[32 * 86];
    __shared__ __align__(16) unsigned sWl[32 * 86];
    int tid = threadIdx.x, lane = tid & 31, w = tid >> 5;
    int mi0 = blockIdx.x * 64;
    int k0  = blockIdx.y * 128;
    int r = lane >> 2, cq = lane & 3;
    int mf = w & 3, ng = w >> 2;
    int tw = mf * 16;

    int mi_l = tid & 63, q = tid >> 6;
    int m = 7679 + mi0 + mi_l;
    float tc2 = 2.0f * cos_ph(m);

    float acc[5][4];
    #pragma unroll
    for (int j = 0; j < 5; j++)
        #pragma unroll
        for (int u = 0; u < 4; u++) acc[j][u] = 0.0f;

    for (int c = 0; c < 2; c++) {
        int kc = k0 + 64 * c;
        int kcH = kc >> 1;
        __syncthreads();
        {
            const uint4* gh = reinterpret_cast<const uint4*>(g_Wh2 + kcH * 86);
            const uint4* gl = reinterpret_cast<const uint4*>(g_Wl2 + kcH * 86);
            uint4* shh = reinterpret_cast<uint4*>(sWh);
            uint4* sll = reinterpret_cast<uint4*>(sWl);
            for (int idx = tid; idx < (32 * 86) / 4; idx += 256) {
                shh[idx] = gh[idx];
                sll[idx] = gl[idx];
            }
        }
        {
            int ks0 = kc + 16 * q;
            int ph = (int)(((long long)ks0 * (long long)m) % IRL);
            float x0 = cos_ph(ph);
            int ph1 = ph + m; if (ph1 >= IRL) ph1 -= IRL;
            float x1 = cos_ph(ph1);
            #pragma unroll
            for (int s = 0; s < 8; s++) {
                sC[(8 * q + s) * 68 + mi_l] = pack_h2(x0, x1);
                float x2 = fmaf(tc2, x1, -x0);
                float x3 = fmaf(tc2, x2, -x1);
                x0 = x2; x1 = x3;
            }
        }
        __syncthreads();
        #pragma unroll
        for (int ks = 0; ks < 4; ks++) {
            int khb = ks * 8;
            unsigned A0 = sC[(khb + cq) * 68 + tw + r];
            unsigned A1 = sC[(khb + cq) * 68 + tw + r + 8];
            unsigned A2 = sC[(khb + cq + 4) * 68 + tw + r];
            unsigned A3 = sC[(khb + cq + 4) * 68 + tw + r + 8];
            #pragma unroll
            for (int j = 0; j < 5; j++) {
                int col = (ng * 5 + j) * 8 + r;
                unsigned B0h = sWh[(khb + cq) * 86 + col];
                unsigned B1h = sWh[(khb + cq + 4) * 86 + col];
                unsigned B0l = sWl[(khb + cq) * 86 + col];
                unsigned B1l = sWl[(khb + cq + 4) * 86 + col];
                HMMA16(acc[j], A0, A1, A2, A3, B0h, B1h);
                HMMA16(acc[j], A0, A1, A2, A3, B0l, B1l);
            }
        }
    }

    int mia = mi0 + tw + r, mib = mia + 8;
    int ja = (mia >= 2) ? (mia - 2) : (1022 - mia);
    int jb = (mib >= 2) ? (mib - 2) : (1022 - mib);
    float sca = (0.5f - 0.5f * cospif((float)(ja + 2) * (1.0f / 512.0f))) * (1.0f / 16382.0f);
    float scb = (0.5f - 0.5f * cospif((float)(jb + 2) * (1.0f / 512.0f))) * (1.0f / 16382.0f);
    #pragma unroll
    for (int j = 0; j < 5; j++) {
        int i0 = (ng * 5 + j) * 8 + 2 * cq;
        if (i0 < NA) {
            atomicAdd(&g_D[mia * NA + i0], acc[j][0] * sca);
            atomicAdd(&g_D[mib * NA + i0], acc[j][2] * scb);
        }
        if (i0 + 1 < NA) {
            atomicAdd(&g_D[mia * NA + i0 + 1], acc[j][1] * sca);
            atomicAdd(&g_D[mib * NA + i0 + 1], acc[j][3] * scb);
        }
    }
}

// ---------------------------------------------------------------------------
// Tensor-core folded FIR, fp16 m16n8k16 (unchanged from R9 WIN).
#define FSTH 136
__global__ void __launch_bounds__(256) k_conv_tc2(const float* __restrict__ eps) {
    __shared__ float    sN[1152];
    __shared__ unsigned sF[16 * FSTH];
    __shared__ unsigned sCf[16 * 72];
    int tid = threadIdx.x;
    int lane = tid & 31, w = tid >> 5;
    int t0 = blockIdx.x * 128;
    int y  = blockIdx.y;
    int c0 = (y == 0) ? 0 : (5 + 4 * (y - 1));
    int c1 = c0 + ((y == 0) ? 5 : 4);

    float mean0 = g_mean[0];
    unsigned encm = g_max_u;
    float gmax = (encm & 0x80000000u) ? __uint_as_float(encm & 0x7fffffffu)
                                      : __uint_as_float(~encm);
    float inv = 1.0f / gmax;
    for (int s = tid; s < 1152; s += 256) {
        int u = t0 - 512 + s;
        sN[s] = (u >= 0 && u < WSZ) ? (mean0 + eps[u]) * inv : 0.0f;
    }

    int r = lane >> 2, cq = lane & 3;
    int tw = w * 16;
    float acc[9][4];
    #pragma unroll
    for (int nf = 0; nf < 9; nf++)
        #pragma unroll
        for (int q = 0; q < 4; q++) acc[nf][q] = 0.0f;

    for (int c = c0; c < c1; c++) {
        int dd0 = 32 * c;
        __syncthreads();
        for (int idx = tid; idx < 16 * 128; idx += 256) {
            int kh = idx >> 7, tt = idx & 127;
            int x = 512 + tt;
            float f[2];
            #pragma unroll
            for (int p = 0; p < 2; p++) {
                int dd = dd0 + 2 * kh + p;
                float v;
                if (dd < 510)       { int d = dd + 1; v = sN[x + d] + sN[x - d]; }
                else if (dd == 510) v = sN[x];
                else if (dd == 511) v = sN[x - 511];
                else if (dd == 512) v = sN[x - 512];
                else                v = 0.0f;
                f[p] = v;
            }
            sF[kh * FSTH + tt] = pack_h2(f[0], f[1]);
        }
        for (int idx = tid; idx < 16 * 72; idx += 256) {
            int kh = idx / 72, i = idx % 72;
            float d[2];
            #pragma unroll
            for (int p = 0; p < 2; p++) {
                int dd = dd0 + 2 * kh + p;
                int mi;
                if (dd < 510)       mi = 511 - dd;
                else if (dd == 510) mi = 512;
                else if (dd == 511) mi = 1;
                else if (dd == 512) mi = 0;
                else                mi = -1;
                d[p] = (mi >= 0 && i < NA) ? g_D[mi * NA + i] : 0.0f;
            }
            sCf[kh * 72 + i] = pack_h2(d[0], d[1]);
        }
        __syncthreads();
        #pragma unroll
        for (int ks = 0; ks < 2; ks++) {
            int kh = ks * 8;
            unsigned a0 = sF[(kh + cq) * FSTH + tw + r];
            unsigned a1 = sF[(kh + cq) * FSTH + tw + r + 8];
            unsigned a2 = sF[(kh + cq + 4) * FSTH + tw + r];
            unsigned a3 = sF[(kh + cq + 4) * FSTH + tw + r + 8];
            #pragma unroll
            for (int nf = 0; nf < 9; nf++) {
                unsigned b0 = sCf[(kh + cq) * 72 + nf * 8 + r];
                unsigned b1 = sCf[(kh + cq + 4) * 72 + nf * 8 + r];
                HMMA16(acc[nf], a0, a1, a2, a3, b0, b1);
            }
        }
    }

    int t = t0 + tw + r;
    #pragma unroll
    for (int nf = 0; nf < 9; nf++) {
        int i0 = nf * 8 + 2 * cq;
        if (i0 < NA) {
            atomicAdd(&g_P[i0 * WSZ + t],     acc[nf][0]);
            atomicAdd(&g_P[i0 * WSZ + t + 8], acc[nf][2]);
        }
        if (i0 + 1 < NA) {
            atomicAdd(&g_P[(i0 + 1) * WSZ + t],     acc[nf][1]);
            atomicAdd(&g_P[(i0 + 1) * WSZ + t + 8], acc[nf][3]);
        }
    }
}

// ---------------------------------------------------------------------------
// k_out via fp16 m16n8k16 (unchanged from R9 WIN).
#define KO_TT 128
#define KO_KH 40
#define PSTH 136
#define XSTH 44
__global__ void __launch_bounds__(256) k_out_tc(const float* __restrict__ vel,
                                                const float* __restrict__ Kin,
                                                float* __restrict__ out) {
    __shared__ unsigned sP[KO_KH * PSTH];
    __shared__ unsigned sX[64 * XSTH];
    __shared__ float    sA[64];
    int tid = threadIdx.x, lane = tid & 31, w = tid >> 5;
    int t0 = blockIdx.x * KO_TT, b0 = blockIdx.y * 64;

    for (int idx = tid; idx < KO_KH * KO_TT; idx += 256) {
        int kh = idx >> 7, tt = idx & 127;
        int i0 = 2 * kh;
        float v0 = (i0     < NA) ? g_P[i0 * WSZ + t0 + tt]       : 0.0f;
        float v1 = (i0 + 1 < NA) ? g_P[(i0 + 1) * WSZ + t0 + tt] : 0.0f;
        sP[kh * PSTH + tt] = pack_h2(v0, v1);
    }
    for (int idx = tid; idx < 64 * KO_KH; idx += 256) {
        int bb = idx / KO_KH, kh = idx % KO_KH;
        int b = b0 + bb;
        float x[2];
        #pragma unroll
        for (int p = 0; p < 2; p++) {
            int i = 2 * kh + p;
            if (i < 64)       x[p] = vel[b * 64 + i];
            else if (i == 64) x[p] = Kin[b] * INV_MAXSTEPS;
            else if (i == 65) x[p] = 1.0f;
            else              x[p] = 0.0f;
        }
        sX[bb * XSTH + kh] = pack_h2(x[0], x[1]);
    }
    if (tid < 64) sA[tid] = g_amps[b0 + tid];
    __syncthreads();

    int wb = w & 1, wt = w >> 1;
    int r = lane >> 2, cq = lane & 3;
    float c[2][4][4];
    #pragma unroll
    for (int mf = 0; mf < 2; mf++)
        #pragma unroll
        for (int nf = 0; nf < 4; nf++)
            #pragma unroll
            for (int q = 0; q < 4; q++) c[mf][nf][q] = 0.0f;

    #pragma unroll
    for (int s = 0; s < KO_KH / 8; s++) {
        int kh = s * 8;
        unsigned a[2][4];
        #pragma unroll
        for (int mf = 0; mf < 2; mf++) {
            int rb = wb * 32 + mf * 16 + r;
            a[mf][0] = sX[rb * XSTH + kh + cq];
            a[mf][1] = sX[(rb + 8) * XSTH + kh + cq];
            a[mf][2] = sX[rb * XSTH + kh + cq + 4];
            a[mf][3] = sX[(rb + 8) * XSTH + kh + cq + 4];
        }
        unsigned bf[4][2];
        #pragma unroll
        for (int nf = 0; nf < 4; nf++) {
            int ct = wt * 32 + nf * 8 + r;
            bf[nf][0] = sP[(kh + cq) * PSTH + ct];
            bf[nf][1] = sP[(kh + cq + 4) * PSTH + ct];
        }
        #pragma unroll
        for (int mf = 0; mf < 2; mf++)
            #pragma unroll
            for (int nf = 0; nf < 4; nf++)
                HMMA16(c[mf][nf], a[mf][0], a[mf][1], a[mf][2], a[mf][3],
                       bf[nf][0], bf[nf][1]);
    }

    #pragma unroll
    for (int mf = 0; mf < 2; mf++) {
        int rbl = wb * 32 + mf * 16 + r;
        float a1 = sA[rbl], a2 = sA[rbl + 8];
        int rb = b0 + rbl;
        #pragma unroll
        for (int nf = 0; nf < 4; nf++) {
            int ct = t0 + wt * 32 + nf * 8 + 2 * cq;
            float2 o1 = make_float2(a1 * c[mf][nf][0], a1 * c[mf][nf][1]);
            float2 o2 = make_float2(a2 * c[mf][nf][2], a2 * c[mf][nf][3]);
            *reinterpret_cast<float2*>(&out[rb * WSZ + ct])       = o1;
            *reinterpret_cast<float2*>(&out[(rb + 8) * WSZ + ct]) = o2;
        }
    }
}

// ---------------------------------------------------------------------------
static cudaStream_t s_aux1, s_aux2;
static cudaEvent_t  ev_root, ev_j1, ev_j2;
namespace {
struct StreamBoot {
    StreamBoot() {
        cudaStreamCreateWithFlags(&s_aux1, cudaStreamNonBlocking);
        cudaStreamCreateWithFlags(&s_aux2, cudaStreamNonBlocking);
        cudaEventCreateWithFlags(&ev_root, cudaEventDisableTiming);
        cudaEventCreateWithFlags(&ev_j1,   cudaEventDisableTiming);
        cudaEventCreateWithFlags(&ev_j2,   cudaEventDisableTiming);
    }
};
static StreamBoot g_stream_boot;
}

extern "C" void kernel_launch(void* const* d_in, const int* in_sizes, int n_in,
                              void* d_out, int out_size) {
    const float* vel = (const float*)d_in[0];
    const float* Kin = (const float*)d_in[1];
    const float* eps = (const float*)d_in[2];
    const float* Wc  = (const float*)d_in[3];
    const float* bc  = (const float*)d_in[4];
    const float* Wa  = (const float*)d_in[5];
    const float* ba  = (const float*)d_in[6];
    const float* Wm  = (const float*)d_in[7];
    const float* bm  = (const float*)d_in[8];
    float* out = (float*)d_out;

    // main: initD -> wprep -> mmat -> (join) -> conv -> out
    k_initD <<< (MI_N * NA + 255) / 256, 256 >>> ();
    cudaEventRecord(ev_root, 0);
    cudaStreamWaitEvent(s_aux1, ev_root, 0);
    cudaStreamWaitEvent(s_aux2, ev_root, 0);

    k_wprep   <<< (4096 * 86 + 255) / 256, 256 >>> (Wc, bc);
    k_mmat_tc <<< dim3(8, MMT_KSPLIT), 256 >>> (Wc, bc);

    // aux1: rowmax (starts at t~0) || stats, then combine
    k_rowmax <<< BATCH, 256, 0, s_aux1 >>> (eps);
    k_stats  <<< 32, 1024, 0, s_aux1 >>> (vel, Kin, Wa, ba, Wm, bm, out, out_size);
    k_combine<<< 1, 1024, 0, s_aux1 >>> ();
    cudaEventRecord(ev_j1, s_aux1);

    // aux2: zero g_P + center column
    k_initP  <<< (NA * WSZ / 4 + 255) / 256, 256, 0, s_aux2 >>> ();
    k_center <<< dim3(NA, 8), 256, 0, s_aux2 >>> (Wc, bc);
    cudaEventRecord(ev_j2, s_aux2);

    cudaStreamWaitEvent(0, ev_j1, 0);
    cudaStreamWaitEvent(0, ev_j2, 0);
    k_conv_tc2<<< dim3(64, 4), 256 >>> (eps);
    k_out_tc  <<< dim3(WSZ / KO_TT, BATCH / 64), 256 >>> (vel, Kin, out);
}